// round 12
// baseline (speedup 1.0000x reference)
#include <cuda_runtime.h>
#include <cuda_bf16.h>
#include <cstdint>

#if defined(__CUDA_ARCH__) && (defined(__CUDA_ARCH_FEAT_SM103_ALL) || defined(__CUDA_ARCH_SPECIFIC__) || defined(__CUDA_ARCH_FAMILY_SPECIFIC__))
#define HAS_TC 1
#else
#define HAS_TC 0
#endif

static constexpr int B_  = 4;
static constexpr int H_  = 64;
static constexpr int W_  = 64;
static constexpr int C_  = 256;
static constexpr int HW_ = H_ * W_;   // 4096
static constexpr int M_  = B_ * HW_;  // 16384

// ---------------- device scratch -------------------------------------------
__device__ float  g_feat0[(size_t)M_ * C_];
__device__ float  g_feat1[(size_t)M_ * C_];
__device__ int4   g_recIdx[(size_t)M_ * 9];
__device__ float4 g_recW[(size_t)M_ * 9];
__device__ __nv_bfloat16 g_wDs[(size_t)3 * 9 * 4 * 2 * 256 * 64];
__device__ __nv_bfloat16 g_wOs[(size_t)4 * 9 * 4 * 2 * 32 * 64];

// ---------------- PTX helpers ----------------------------------------------
__device__ __forceinline__ uint32_t smem_u32(const void* p) {
    uint32_t a;
    asm("{ .reg .u64 t; cvta.to.shared.u64 t, %1; cvt.u32.u64 %0, t; }" : "=r"(a) : "l"(p));
    return a;
}
#if HAS_TC
__device__ __forceinline__ void mbar_init(uint32_t a, uint32_t cnt) {
    asm volatile("mbarrier.init.shared.b64 [%0], %1;" :: "r"(a), "r"(cnt) : "memory");
}
__device__ __forceinline__ void mbar_wait(uint32_t a, uint32_t phase) {
    asm volatile(
        "{\n\t.reg .pred P;\n\t"
        "WL_%=:\n\t"
        "mbarrier.try_wait.parity.acquire.cta.shared::cta.b64 P, [%0], %1, 0x989680;\n\t"
        "@P bra.uni WD_%=;\n\t"
        "bra.uni WL_%=;\n\t"
        "WD_%=:\n\t}"
        :: "r"(a), "r"(phase) : "memory");
}
__device__ __forceinline__ void tc_commit(uint32_t mbar) {
    asm volatile(
        "tcgen05.commit.cta_group::1.mbarrier::arrive::one.shared::cluster.b64 [%0];"
        :: "r"(mbar) : "memory");
}
__device__ __forceinline__ void mma_f16_ss(uint32_t d, uint64_t ad, uint64_t bd,
                                           uint32_t idesc, uint32_t en) {
    asm volatile(
        "{\n\t.reg .pred p;\n\t"
        "setp.ne.u32 p, %4, 0;\n\t"
        "tcgen05.mma.cta_group::1.kind::f16 [%0], %1, %2, %3, {%5,%5,%5,%5}, p;\n\t}"
        :: "r"(d), "l"(ad), "l"(bd), "r"(idesc), "r"(en), "r"(0u) : "memory");
}
// split pair (a,b) into packed bf16 hi-pair and lo-pair
__device__ __forceinline__ void split2(float a, float b, uint32_t& hp, uint32_t& lp) {
    asm("cvt.rn.bf16x2.f32 %0, %1, %2;" : "=r"(hp) : "f"(b), "f"(a));
    float fa = __uint_as_float(hp << 16);
    float fb = __uint_as_float(hp & 0xFFFF0000u);
    float la = a - fa, lb = b - fb;
    asm("cvt.rn.bf16x2.f32 %0, %1, %2;" : "=r"(lp) : "f"(lb), "f"(la));
}
#define LDTM_X32(r, addr) \
    asm volatile( \
        "tcgen05.ld.sync.aligned.32x32b.x32.b32 " \
        "{%0,%1,%2,%3,%4,%5,%6,%7,%8,%9,%10,%11,%12,%13,%14,%15," \
        "%16,%17,%18,%19,%20,%21,%22,%23,%24,%25,%26,%27,%28,%29,%30,%31}, [%32];" \
        : "=r"((r)[0]),"=r"((r)[1]),"=r"((r)[2]),"=r"((r)[3]), \
          "=r"((r)[4]),"=r"((r)[5]),"=r"((r)[6]),"=r"((r)[7]), \
          "=r"((r)[8]),"=r"((r)[9]),"=r"((r)[10]),"=r"((r)[11]), \
          "=r"((r)[12]),"=r"((r)[13]),"=r"((r)[14]),"=r"((r)[15]), \
          "=r"((r)[16]),"=r"((r)[17]),"=r"((r)[18]),"=r"((r)[19]), \
          "=r"((r)[20]),"=r"((r)[21]),"=r"((r)[22]),"=r"((r)[23]), \
          "=r"((r)[24]),"=r"((r)[25]),"=r"((r)[26]),"=r"((r)[27]), \
          "=r"((r)[28]),"=r"((r)[29]),"=r"((r)[30]),"=r"((r)[31]) \
        : "r"(addr))
#endif

// ---------------- pack: NCHW x,y -> NHWC concat feat0 ----------------------
__global__ void pack_kernel(const float* __restrict__ x, const float* __restrict__ y)
{
    __shared__ float t[32][33];
    int b = blockIdx.z, hw0 = blockIdx.x * 32, c0 = blockIdx.y * 32;
    int tx = threadIdx.x, ty = threadIdx.y;
#pragma unroll
    for (int i = 0; i < 32; i += 8) {
        int c = c0 + ty + i;
        const float* s = (c < 128) ? (x + ((size_t)b * 128 + c) * HW_)
                                   : (y + ((size_t)b * 128 + (c - 128)) * HW_);
        t[ty + i][tx] = s[hw0 + tx];
    }
    __syncthreads();
#pragma unroll
    for (int i = 0; i < 32; i += 8)
        g_feat0[((size_t)b * HW_ + hw0 + ty + i) * C_ + c0 + tx] = t[tx][ty + i];
}

// ---------------- weight split + pre-swizzle --------------------------------
__global__ void wsplit_kernel(const float* __restrict__ oW, const float* __restrict__ dW)
{
#if HAS_TC
    const int GD = 3 * 9 * 4 * 2048;
    const int GO = 4 * 9 * 4 * 256;
    int g = blockIdx.x * blockDim.x + threadIdx.x;
    if (g >= GD + GO) return;
    if (g < GD) {
        int t = g >> 11, o = g & 2047;
        int chunk = t & 3, tap = (t >> 2) % 9, it = (t >> 2) / 9;
        uint32_t boff = (uint32_t)o * 16;
        uint32_t un = boff ^ ((boff >> 3) & 0x70);
        int n = un >> 7, k0 = (un & 127) >> 1;
        uint32_t hp[4], lp[4];
#pragma unroll
        for (int j2 = 0; j2 < 4; j2++) {
            float v0 = dW[((size_t)(it * 256 + n) * 256 + (size_t)(chunk * 64 + k0 + j2 * 2)) * 9 + tap];
            float v1 = dW[((size_t)(it * 256 + n) * 256 + (size_t)(chunk * 64 + k0 + j2 * 2 + 1)) * 9 + tap];
            split2(v0, v1, hp[j2], lp[j2]);
        }
        char* base = (char*)(g_wDs + (size_t)(((it * 9 + tap) * 4 + chunk) * 2) * 16384);
        *(uint4*)(base + boff)         = make_uint4(hp[0], hp[1], hp[2], hp[3]);
        *(uint4*)(base + 32768 + boff) = make_uint4(lp[0], lp[1], lp[2], lp[3]);
    } else {
        int g2 = g - GD;
        int t = g2 >> 8, o = g2 & 255;
        int chunk = t & 3, tap = (t >> 2) % 9, it = (t >> 2) / 9;
        uint32_t boff = (uint32_t)o * 16;
        uint32_t un = boff ^ ((boff >> 3) & 0x70);
        int n = un >> 7, k0 = (un & 127) >> 1;
        uint32_t hp[4], lp[4];
#pragma unroll
        for (int j2 = 0; j2 < 4; j2++) {
            float v0 = (n < 18) ? oW[((size_t)(it * 18 + n) * 256 + (size_t)(chunk * 64 + k0 + j2 * 2)) * 9 + tap] : 0.f;
            float v1 = (n < 18) ? oW[((size_t)(it * 18 + n) * 256 + (size_t)(chunk * 64 + k0 + j2 * 2 + 1)) * 9 + tap] : 0.f;
            split2(v0, v1, hp[j2], lp[j2]);
        }
        char* base = (char*)(g_wOs + (size_t)(((it * 9 + tap) * 4 + chunk) * 2) * 2048);
        *(uint4*)(base + boff)        = make_uint4(hp[0], hp[1], hp[2], hp[3]);
        *(uint4*)(base + 4096 + boff) = make_uint4(lp[0], lp[1], lp[2], lp[3]);
    }
#endif
}

#if HAS_TC
// shared coords math: offsets (dy,dx) for pixel m, tap k -> gather record
__device__ __forceinline__ void make_record(int m, int k, float dy, float dx)
{
    int b = m >> 12, hw = m & 4095, h = hw >> 6, w = hw & 63;
    float py = dy + (float)(k / 3 - 1) + (float)h;
    float px = dx + (float)(k % 3 - 1) + (float)w;
    float y0f = floorf(py), x0f = floorf(px);
    float wy1 = py - y0f, wy0 = 1.f - wy1;
    float wx1 = px - x0f, wx0 = 1.f - wx1;
    int y0 = (int)y0f, x0 = (int)x0f, y1 = y0 + 1, x1 = x0 + 1;
    int4 ii; float4 ww;
    {
        bool v = (y0 >= 0 && y0 < H_ && x0 >= 0 && x0 < W_);
        int yc = min(max(y0,0),H_-1), xc = min(max(x0,0),W_-1);
        ii.x = ((b << 12) + (yc << 6) + xc) << 8;  ww.x = v ? wy0 * wx0 : 0.f;
    }
    {
        bool v = (y0 >= 0 && y0 < H_ && x1 >= 0 && x1 < W_);
        int yc = min(max(y0,0),H_-1), xc = min(max(x1,0),W_-1);
        ii.y = ((b << 12) + (yc << 6) + xc) << 8;  ww.y = v ? wy0 * wx1 : 0.f;
    }
    {
        bool v = (y1 >= 0 && y1 < H_ && x0 >= 0 && x0 < W_);
        int yc = min(max(y1,0),H_-1), xc = min(max(x0,0),W_-1);
        ii.z = ((b << 12) + (yc << 6) + xc) << 8;  ww.z = v ? wy1 * wx0 : 0.f;
    }
    {
        bool v = (y1 >= 0 && y1 < H_ && x1 >= 0 && x1 < W_);
        int yc = min(max(y1,0),H_-1), xc = min(max(x1,0),W_-1);
        ii.w = ((b << 12) + (yc << 6) + xc) << 8;  ww.w = v ? wy1 * wx1 : 0.f;
    }
    g_recIdx[(size_t)m * 9 + k] = ii;
    g_recW[(size_t)m * 9 + k]   = ww;
}
#endif

// ================= offset conv (N=32), 4-deep pipeline, fused coords =======
__global__ __launch_bounds__(256)
void offconv_kernel(int fsel, int wsel, float* __restrict__ finalOut)
{
#if HAS_TC
    constexpr int NB = 32 * 128;   // 4 KB per split
    constexpr uint32_t IDESC =
        (1u << 4) | (1u << 7) | (1u << 10) | (4u << 17) | (8u << 24);

    extern __shared__ char smem[];
    const uint32_t sb = smem_u32(smem);
    const int TMEMP = 0, MBAR = 16, SIDX = 64;
    const int ABASE = 8192;                 // 4 stages x 2 splits x 16KB
    const int BBASE = 8192 + 131072;        // 4 stages x 2 splits x 4KB

    const float* __restrict__ fin = fsel ? g_feat1 : g_feat0;
    const __nv_bfloat16* __restrict__ wsrc = g_wOs + (size_t)wsel * 9 * 4 * 2 * 2048;

    const int tid = threadIdx.x, wid = tid >> 5, lid = tid & 31;
    const int bm0 = blockIdx.x * 128;

    if (wid == 0) {
        asm volatile("tcgen05.alloc.cta_group::1.sync.aligned.shared::cta.b32 [%0], %1;"
                     :: "r"(sb + TMEMP), "r"(128u) : "memory");
        asm volatile("tcgen05.relinquish_alloc_permit.cta_group::1.sync.aligned;");
    }
    if (tid < 4) mbar_init(sb + MBAR + 8 * tid, 1);
    // preload all 9 taps' base indices
    for (int t = tid; t < 9 * 128; t += 256) {
        int tap = t >> 7, p = t & 127;
        int m = bm0 + p;
        int b = m >> 12, hw = m & 4095, h = hw >> 6, w = hw & 63;
        int yy = h + tap / 3 - 1, xx = w + tap % 3 - 1;
        ((int*)(smem + SIDX))[t] =
            (yy >= 0 && yy < H_ && xx >= 0 && xx < W_)
                ? (((b << 12) + (yy << 6) + xx) << 8) : -1;
    }
    __syncthreads();
    uint32_t tb;
    asm volatile("ld.shared.b32 %0, [%1];" : "=r"(tb) : "r"(sb + TMEMP));

    const int cl4 = (lid & 15) * 4;
    const int ph  = (lid >> 4);

    for (int ks = 0; ks < 36; ++ks) {
        const int tap = ks >> 2, ch = ks & 3;
        const int buf = ks & 3;
        const int uses = ks >> 2;
        if (uses > 0) mbar_wait(sb + MBAR + 8 * buf, (uses - 1) & 1);

        // B tile (1 float4 per thread per split)
        {
            const char* bsh = (const char*)(wsrc + (size_t)(ks * 2) * 2048);
            ((float4*)(smem + BBASE + (buf * 2 + 0) * NB))[tid] = ((const float4*)bsh)[tid];
            ((float4*)(smem + BBASE + (buf * 2 + 1) * NB))[tid] = ((const float4*)(bsh + NB))[tid];
        }
        // A tile
        {
            char* ah = smem + ABASE + (buf * 2 + 0) * 16384;
            char* al = smem + ABASE + (buf * 2 + 1) * 16384;
            const int co = ch * 64 + cl4;
            const int* sidx = (const int*)(smem + SIDX) + tap * 128;
#pragma unroll
            for (int pass = 0; pass < 8; ++pass) {
                int p = pass * 16 + wid * 2 + ph;
                int base = sidx[p];
                float4 r = make_float4(0.f, 0.f, 0.f, 0.f);
                if (base >= 0) r = *(const float4*)(fin + base + co);
                uint2 hp, lp;
                split2(r.x, r.y, hp.x, lp.x);
                split2(r.z, r.w, hp.y, lp.y);
                uint32_t o  = (uint32_t)(p * 128 + (lid & 15) * 8);
                uint32_t so = o ^ ((o >> 3) & 0x70);
                *(uint2*)(ah + so) = hp;
                *(uint2*)(al + so) = lp;
            }
        }
        asm volatile("fence.proxy.async.shared::cta;" ::: "memory");
        __syncthreads();

        if (tid == 0) {
            asm volatile("tcgen05.fence::after_thread_sync;" ::: "memory");
            const uint64_t DB = (2ull << 61) | (1ull << 46) | (64ull << 32) | (1ull << 16);
            uint64_t adh = DB | (((sb + ABASE + (buf * 2 + 0) * 16384) >> 4) & 0x3FFF);
            uint64_t adl = DB | (((sb + ABASE + (buf * 2 + 1) * 16384) >> 4) & 0x3FFF);
            uint64_t bdh = DB | (((sb + BBASE + (buf * 2 + 0) * NB) >> 4) & 0x3FFF);
            uint64_t bdl = DB | (((sb + BBASE + (buf * 2 + 1) * NB) >> 4) & 0x3FFF);
#pragma unroll
            for (int k4 = 0; k4 < 4; k4++)
                mma_f16_ss(tb, adh + 2 * k4, bdh + 2 * k4, IDESC, (ks | k4) != 0);
#pragma unroll
            for (int k4 = 0; k4 < 4; k4++)
                mma_f16_ss(tb, adh + 2 * k4, bdl + 2 * k4, IDESC, 1);
#pragma unroll
            for (int k4 = 0; k4 < 4; k4++)
                mma_f16_ss(tb, adl + 2 * k4, bdh + 2 * k4, IDESC, 1);
            tc_commit(sb + MBAR + 8 * buf);
        }
    }

    // last commit (ks=35, buf=3, 9th completion -> parity 0) implies all done
    mbar_wait(sb + MBAR + 8 * 3, 0);
    asm volatile("tcgen05.fence::after_thread_sync;" ::: "memory");

    if (tid < 128) {
        int m = bm0 + wid * 32 + lid;
        uint32_t r[32];
        LDTM_X32(r, tb);
        asm volatile("tcgen05.wait::ld.sync.aligned;" ::: "memory");
        if (finalOut) {
            int b = m >> 12, hw = m & 4095;
#pragma unroll
            for (int j = 0; j < 18; j++)
                finalOut[((size_t)(b * 18 + j)) * HW_ + hw] = __uint_as_float(r[j]);
        } else {
#pragma unroll
            for (int k = 0; k < 9; k++)
                make_record(m, k, __uint_as_float(r[2 * k]), __uint_as_float(r[2 * k + 1]));
        }
    }
    __syncthreads();
    if (wid == 0)
        asm volatile("tcgen05.dealloc.cta_group::1.sync.aligned.b32 %0, %1;"
                     :: "r"(tb), "r"(128u));
#endif
}

// ================= deform conv (N=256), 2-deep pipeline =====================
__global__ __launch_bounds__(256)
void defconv_kernel(int fsel, int wsel)
{
#if HAS_TC
    constexpr int NB = 256 * 128;   // 32 KB per split
    constexpr uint32_t IDESC =
        (1u << 4) | (1u << 7) | (1u << 10) | (32u << 17) | (8u << 24);

    extern __shared__ char smem[];
    const uint32_t sb = smem_u32(smem);
    const int TMEMP = 0, MBAR = 16, SIDX = 64, SWT = 64 + 2048;
    const int ABASE = 8192;          // 2 stages x 2 splits x 16KB = 64KB
    const int BBASE = 8192 + 65536;  // 2 stages x 2 splits x 32KB = 128KB

    const float* __restrict__ fin = fsel ? g_feat1 : g_feat0;
    float* __restrict__ fout      = fsel ? g_feat0 : g_feat1;
    const __nv_bfloat16* __restrict__ wsrc = g_wDs + (size_t)wsel * 9 * 4 * 2 * 16384;

    const int tid = threadIdx.x, wid = tid >> 5, lid = tid & 31;
    const int bm0 = blockIdx.x * 128;

    if (wid == 0) {
        asm volatile("tcgen05.alloc.cta_group::1.sync.aligned.shared::cta.b32 [%0], %1;"
                     :: "r"(sb + TMEMP), "r"(512u) : "memory");
        asm volatile("tcgen05.relinquish_alloc_permit.cta_group::1.sync.aligned;");
    }
    if (tid < 2) mbar_init(sb + MBAR + 8 * tid, 1);
    __syncthreads();
    uint32_t tb;
    asm volatile("ld.shared.b32 %0, [%1];" : "=r"(tb) : "r"(sb + TMEMP));

    int use0 = 0, use1 = 0;
    const int cl4 = (lid & 15) * 4;
    const int ph  = (lid >> 4);

    for (int tap = 0; tap < 9; ++tap) {
        if (tid < 128) {
            int m = bm0 + tid;
            ((int4*)(smem + SIDX))[tid]  = g_recIdx[(size_t)m * 9 + tap];
            ((float4*)(smem + SWT))[tid] = g_recW[(size_t)m * 9 + tap];
        }
        __syncthreads();

        for (int ch = 0; ch < 4; ++ch) {
            const int ks = tap * 4 + ch;
            const int buf = ks & 1;
            int& u = buf ? use1 : use0;
            if (u > 0) mbar_wait(sb + MBAR + 8 * buf, (u - 1) & 1);

            {
                const char* bsh = (const char*)(wsrc + (size_t)(ks * 2) * 16384);
                float4* dh = (float4*)(smem + BBASE + (buf * 2 + 0) * NB);
                float4* dl = (float4*)(smem + BBASE + (buf * 2 + 1) * NB);
                const float4* sh = (const float4*)bsh;
                const float4* sl = (const float4*)(bsh + NB);
#pragma unroll
                for (int q0 = 0; q0 < NB / 16; q0 += 256) {
                    dh[q0 + tid] = sh[q0 + tid];
                    dl[q0 + tid] = sl[q0 + tid];
                }
            }
            {
                char* ah = smem + ABASE + (buf * 2 + 0) * 16384;
                char* al = smem + ABASE + (buf * 2 + 1) * 16384;
                const int co = ch * 64 + cl4;
#pragma unroll
                for (int pass = 0; pass < 8; ++pass) {
                    int p = pass * 16 + wid * 2 + ph;
                    int4   ii = ((const int4*)(smem + SIDX))[p];
                    float4 wt = ((const float4*)(smem + SWT))[p];
                    float4 a = *(const float4*)(fin + ii.x + co);
                    float4 b = *(const float4*)(fin + ii.y + co);
                    float4 c = *(const float4*)(fin + ii.z + co);
                    float4 d = *(const float4*)(fin + ii.w + co);
                    float4 r;
                    r.x = wt.x*a.x + wt.y*b.x + wt.z*c.x + wt.w*d.x;
                    r.y = wt.x*a.y + wt.y*b.y + wt.z*c.y + wt.w*d.y;
                    r.z = wt.x*a.z + wt.y*b.z + wt.z*c.z + wt.w*d.z;
                    r.w = wt.x*a.w + wt.y*b.w + wt.z*c.w + wt.w*d.w;
                    uint2 hp, lp;
                    split2(r.x, r.y, hp.x, lp.x);
                    split2(r.z, r.w, hp.y, lp.y);
                    uint32_t o  = (uint32_t)(p * 128 + (lid & 15) * 8);
                    uint32_t so = o ^ ((o >> 3) & 0x70);
                    *(uint2*)(ah + so) = hp;
                    *(uint2*)(al + so) = lp;
                }
            }
            asm volatile("fence.proxy.async.shared::cta;" ::: "memory");
            __syncthreads();

            if (tid == 0) {
                asm volatile("tcgen05.fence::after_thread_sync;" ::: "memory");
                const uint64_t DB = (2ull << 61) | (1ull << 46) | (64ull << 32) | (1ull << 16);
                uint64_t adh = DB | (((sb + ABASE + (buf * 2 + 0) * 16384) >> 4) & 0x3FFF);
                uint64_t adl = DB | (((sb + ABASE + (buf * 2 + 1) * 16384) >> 4) & 0x3FFF);
                uint64_t bdh = DB | (((sb + BBASE + (buf * 2 + 0) * NB) >> 4) & 0x3FFF);
                uint64_t bdl = DB | (((sb + BBASE + (buf * 2 + 1) * NB) >> 4) & 0x3FFF);
#pragma unroll
                for (int k4 = 0; k4 < 4; k4++)
                    mma_f16_ss(tb, adh + 2 * k4, bdh + 2 * k4, IDESC, (ks | k4) != 0);
#pragma unroll
                for (int k4 = 0; k4 < 4; k4++)
                    mma_f16_ss(tb, adh + 2 * k4, bdl + 2 * k4, IDESC, 1);
#pragma unroll
                for (int k4 = 0; k4 < 4; k4++)
                    mma_f16_ss(tb, adl + 2 * k4, bdh + 2 * k4, IDESC, 1);
                tc_commit(sb + MBAR + 8 * buf);
            }
            u++;
        }
    }

    // last commit on buf1 (18th completion -> parity 1) implies all done
    mbar_wait(sb + MBAR + 8, 1);
    asm volatile("tcgen05.fence::after_thread_sync;" ::: "memory");

    if (tid < 128) {
        int m = bm0 + wid * 32 + lid;
#pragma unroll
        for (int nb = 0; nb < 8; nb++) {
            uint32_t r[32];
            LDTM_X32(r, tb + nb * 32);
            asm volatile("tcgen05.wait::ld.sync.aligned;" ::: "memory");
            float4* dst = (float4*)(fout + (size_t)m * 256 + nb * 32);
#pragma unroll
            for (int q = 0; q < 8; q++)
                dst[q] = make_float4(__uint_as_float(r[q*4+0]), __uint_as_float(r[q*4+1]),
                                     __uint_as_float(r[q*4+2]), __uint_as_float(r[q*4+3]));
        }
    }
    __syncthreads();
    if (wid == 0)
        asm volatile("tcgen05.dealloc.cta_group::1.sync.aligned.b32 %0, %1;"
                     :: "r"(tb), "r"(512u));
#endif
}

// ---------------------------------------------------------------------------
extern "C" void kernel_launch(void* const* d_in, const int* in_sizes, int n_in,
                              void* d_out, int out_size)
{
    (void)in_sizes; (void)n_in; (void)out_size;
    const float* x  = (const float*)d_in[0];
    const float* y  = (const float*)d_in[1];
    const float* oW = (const float*)d_in[2];
    const float* dW = (const float*)d_in[3];
    float* out = (float*)d_out;

    const int SMEM_D = 8192 + 65536 + 131072;   // 204800
    const int SMEM_O = 8192 + 131072 + 32768;   // 172032
    cudaFuncSetAttribute(defconv_kernel, cudaFuncAttributeMaxDynamicSharedMemorySize, SMEM_D);
    cudaFuncSetAttribute(offconv_kernel, cudaFuncAttributeMaxDynamicSharedMemorySize, SMEM_O);

    dim3 pb(32, 8), pg(HW_ / 32, C_ / 32, B_);
    pack_kernel<<<pg, pb>>>(x, y);

    const int G = 3 * 9 * 4 * 2048 + 4 * 9 * 4 * 256;
    wsplit_kernel<<<(G + 255) / 256, 256>>>(oW, dW);

    int fsel = 0;
    for (int it = 0; it < 3; ++it) {
        offconv_kernel<<<128, 256, SMEM_O>>>(fsel, it, nullptr);
        defconv_kernel<<<128, 256, SMEM_D>>>(fsel, it);
        fsel ^= 1;
    }
    offconv_kernel<<<128, 256, SMEM_O>>>(fsel, 3, out);
}

// round 13
// speedup vs baseline: 1.0159x; 1.0159x over previous
#include <cuda_runtime.h>
#include <cuda_bf16.h>
#include <cstdint>

#if defined(__CUDA_ARCH__) && (defined(__CUDA_ARCH_FEAT_SM103_ALL) || defined(__CUDA_ARCH_SPECIFIC__) || defined(__CUDA_ARCH_FAMILY_SPECIFIC__))
#define HAS_TC 1
#else
#define HAS_TC 0
#endif

static constexpr int B_  = 4;
static constexpr int H_  = 64;
static constexpr int W_  = 64;
static constexpr int C_  = 256;
static constexpr int HW_ = H_ * W_;   // 4096
static constexpr int M_  = B_ * HW_;  // 16384

// ---------------- device scratch -------------------------------------------
__device__ float  g_feat0[(size_t)M_ * C_];
__device__ float  g_feat1[(size_t)M_ * C_];
__device__ int4   g_recIdx[(size_t)M_ * 9];
__device__ float4 g_recW[(size_t)M_ * 9];
__device__ __nv_bfloat16 g_wDs[(size_t)3 * 9 * 4 * 2 * 256 * 64];
__device__ __nv_bfloat16 g_wOs[(size_t)4 * 9 * 4 * 2 * 32 * 64];

// ---------------- PTX helpers ----------------------------------------------
__device__ __forceinline__ uint32_t smem_u32(const void* p) {
    uint32_t a;
    asm("{ .reg .u64 t; cvta.to.shared.u64 t, %1; cvt.u32.u64 %0, t; }" : "=r"(a) : "l"(p));
    return a;
}
#if HAS_TC
__device__ __forceinline__ void mbar_init(uint32_t a, uint32_t cnt) {
    asm volatile("mbarrier.init.shared.b64 [%0], %1;" :: "r"(a), "r"(cnt) : "memory");
}
__device__ __forceinline__ void mbar_wait(uint32_t a, uint32_t phase) {
    asm volatile(
        "{\n\t.reg .pred P;\n\t"
        "WL_%=:\n\t"
        "mbarrier.try_wait.parity.acquire.cta.shared::cta.b64 P, [%0], %1, 0x989680;\n\t"
        "@P bra.uni WD_%=;\n\t"
        "bra.uni WL_%=;\n\t"
        "WD_%=:\n\t}"
        :: "r"(a), "r"(phase) : "memory");
}
__device__ __forceinline__ void tc_commit(uint32_t mbar) {
    asm volatile(
        "tcgen05.commit.cta_group::1.mbarrier::arrive::one.shared::cluster.b64 [%0];"
        :: "r"(mbar) : "memory");
}
__device__ __forceinline__ void mma_f16_ss(uint32_t d, uint64_t ad, uint64_t bd,
                                           uint32_t idesc, uint32_t en) {
    asm volatile(
        "{\n\t.reg .pred p;\n\t"
        "setp.ne.u32 p, %4, 0;\n\t"
        "tcgen05.mma.cta_group::1.kind::f16 [%0], %1, %2, %3, {%5,%5,%5,%5}, p;\n\t}"
        :: "r"(d), "l"(ad), "l"(bd), "r"(idesc), "r"(en), "r"(0u) : "memory");
}
// split pair (a,b) into packed bf16 hi-pair and lo-pair
__device__ __forceinline__ void split2(float a, float b, uint32_t& hp, uint32_t& lp) {
    asm("cvt.rn.bf16x2.f32 %0, %1, %2;" : "=r"(hp) : "f"(b), "f"(a));
    float fa = __uint_as_float(hp << 16);
    float fb = __uint_as_float(hp & 0xFFFF0000u);
    float la = a - fa, lb = b - fb;
    asm("cvt.rn.bf16x2.f32 %0, %1, %2;" : "=r"(lp) : "f"(lb), "f"(la));
}
#define LDTM_X32(r, addr) \
    asm volatile( \
        "tcgen05.ld.sync.aligned.32x32b.x32.b32 " \
        "{%0,%1,%2,%3,%4,%5,%6,%7,%8,%9,%10,%11,%12,%13,%14,%15," \
        "%16,%17,%18,%19,%20,%21,%22,%23,%24,%25,%26,%27,%28,%29,%30,%31}, [%32];" \
        : "=r"((r)[0]),"=r"((r)[1]),"=r"((r)[2]),"=r"((r)[3]), \
          "=r"((r)[4]),"=r"((r)[5]),"=r"((r)[6]),"=r"((r)[7]), \
          "=r"((r)[8]),"=r"((r)[9]),"=r"((r)[10]),"=r"((r)[11]), \
          "=r"((r)[12]),"=r"((r)[13]),"=r"((r)[14]),"=r"((r)[15]), \
          "=r"((r)[16]),"=r"((r)[17]),"=r"((r)[18]),"=r"((r)[19]), \
          "=r"((r)[20]),"=r"((r)[21]),"=r"((r)[22]),"=r"((r)[23]), \
          "=r"((r)[24]),"=r"((r)[25]),"=r"((r)[26]),"=r"((r)[27]), \
          "=r"((r)[28]),"=r"((r)[29]),"=r"((r)[30]),"=r"((r)[31]) \
        : "r"(addr))
#endif

// ---------------- pack: NCHW x,y -> NHWC concat feat0 ----------------------
__global__ void pack_kernel(const float* __restrict__ x, const float* __restrict__ y)
{
    __shared__ float t[32][33];
    int b = blockIdx.z, hw0 = blockIdx.x * 32, c0 = blockIdx.y * 32;
    int tx = threadIdx.x, ty = threadIdx.y;
#pragma unroll
    for (int i = 0; i < 32; i += 8) {
        int c = c0 + ty + i;
        const float* s = (c < 128) ? (x + ((size_t)b * 128 + c) * HW_)
                                   : (y + ((size_t)b * 128 + (c - 128)) * HW_);
        t[ty + i][tx] = s[hw0 + tx];
    }
    __syncthreads();
#pragma unroll
    for (int i = 0; i < 32; i += 8)
        g_feat0[((size_t)b * HW_ + hw0 + ty + i) * C_ + c0 + tx] = t[tx][ty + i];
}

// ---------------- weight split + pre-swizzle --------------------------------
__global__ void wsplit_kernel(const float* __restrict__ oW, const float* __restrict__ dW)
{
#if HAS_TC
    const int GD = 3 * 9 * 4 * 2048;
    const int GO = 4 * 9 * 4 * 256;
    int g = blockIdx.x * blockDim.x + threadIdx.x;
    if (g >= GD + GO) return;
    if (g < GD) {
        int t = g >> 11, o = g & 2047;
        int chunk = t & 3, tap = (t >> 2) % 9, it = (t >> 2) / 9;
        uint32_t boff = (uint32_t)o * 16;
        uint32_t un = boff ^ ((boff >> 3) & 0x70);
        int n = un >> 7, k0 = (un & 127) >> 1;
        uint32_t hp[4], lp[4];
#pragma unroll
        for (int j2 = 0; j2 < 4; j2++) {
            float v0 = dW[((size_t)(it * 256 + n) * 256 + (size_t)(chunk * 64 + k0 + j2 * 2)) * 9 + tap];
            float v1 = dW[((size_t)(it * 256 + n) * 256 + (size_t)(chunk * 64 + k0 + j2 * 2 + 1)) * 9 + tap];
            split2(v0, v1, hp[j2], lp[j2]);
        }
        char* base = (char*)(g_wDs + (size_t)(((it * 9 + tap) * 4 + chunk) * 2) * 16384);
        *(uint4*)(base + boff)         = make_uint4(hp[0], hp[1], hp[2], hp[3]);
        *(uint4*)(base + 32768 + boff) = make_uint4(lp[0], lp[1], lp[2], lp[3]);
    } else {
        int g2 = g - GD;
        int t = g2 >> 8, o = g2 & 255;
        int chunk = t & 3, tap = (t >> 2) % 9, it = (t >> 2) / 9;
        uint32_t boff = (uint32_t)o * 16;
        uint32_t un = boff ^ ((boff >> 3) & 0x70);
        int n = un >> 7, k0 = (un & 127) >> 1;
        uint32_t hp[4], lp[4];
#pragma unroll
        for (int j2 = 0; j2 < 4; j2++) {
            float v0 = (n < 18) ? oW[((size_t)(it * 18 + n) * 256 + (size_t)(chunk * 64 + k0 + j2 * 2)) * 9 + tap] : 0.f;
            float v1 = (n < 18) ? oW[((size_t)(it * 18 + n) * 256 + (size_t)(chunk * 64 + k0 + j2 * 2 + 1)) * 9 + tap] : 0.f;
            split2(v0, v1, hp[j2], lp[j2]);
        }
        char* base = (char*)(g_wOs + (size_t)(((it * 9 + tap) * 4 + chunk) * 2) * 2048);
        *(uint4*)(base + boff)        = make_uint4(hp[0], hp[1], hp[2], hp[3]);
        *(uint4*)(base + 4096 + boff) = make_uint4(lp[0], lp[1], lp[2], lp[3]);
    }
#endif
}

#if HAS_TC
// shared coords math: offsets (dy,dx) for pixel m, tap k -> gather record
__device__ __forceinline__ void make_record(int m, int k, float dy, float dx)
{
    int b = m >> 12, hw = m & 4095, h = hw >> 6, w = hw & 63;
    float py = dy + (float)(k / 3 - 1) + (float)h;
    float px = dx + (float)(k % 3 - 1) + (float)w;
    float y0f = floorf(py), x0f = floorf(px);
    float wy1 = py - y0f, wy0 = 1.f - wy1;
    float wx1 = px - x0f, wx0 = 1.f - wx1;
    int y0 = (int)y0f, x0 = (int)x0f, y1 = y0 + 1, x1 = x0 + 1;
    int4 ii; float4 ww;
    {
        bool v = (y0 >= 0 && y0 < H_ && x0 >= 0 && x0 < W_);
        int yc = min(max(y0,0),H_-1), xc = min(max(x0,0),W_-1);
        ii.x = ((b << 12) + (yc << 6) + xc) << 8;  ww.x = v ? wy0 * wx0 : 0.f;
    }
    {
        bool v = (y0 >= 0 && y0 < H_ && x1 >= 0 && x1 < W_);
        int yc = min(max(y0,0),H_-1), xc = min(max(x1,0),W_-1);
        ii.y = ((b << 12) + (yc << 6) + xc) << 8;  ww.y = v ? wy0 * wx1 : 0.f;
    }
    {
        bool v = (y1 >= 0 && y1 < H_ && x0 >= 0 && x0 < W_);
        int yc = min(max(y1,0),H_-1), xc = min(max(x0,0),W_-1);
        ii.z = ((b << 12) + (yc << 6) + xc) << 8;  ww.z = v ? wy1 * wx0 : 0.f;
    }
    {
        bool v = (y1 >= 0 && y1 < H_ && x1 >= 0 && x1 < W_);
        int yc = min(max(y1,0),H_-1), xc = min(max(x1,0),W_-1);
        ii.w = ((b << 12) + (yc << 6) + xc) << 8;  ww.w = v ? wy1 * wx1 : 0.f;
    }
    g_recIdx[(size_t)m * 9 + k] = ii;
    g_recW[(size_t)m * 9 + k]   = ww;
}
#endif

// ================= offset conv (N=32), 4-deep pipeline, fused coords =======
__global__ __launch_bounds__(256)
void offconv_kernel(int fsel, int wsel, float* __restrict__ finalOut)
{
#if HAS_TC
    constexpr int NB = 32 * 128;   // 4 KB per split
    constexpr uint32_t IDESC =
        (1u << 4) | (1u << 7) | (1u << 10) | (4u << 17) | (8u << 24);

    extern __shared__ char smem[];
    const uint32_t sb = smem_u32(smem);
    const int TMEMP = 0, MBAR = 16, SIDX = 64;
    const int ABASE = 8192;                 // 4 stages x 2 splits x 16KB
    const int BBASE = 8192 + 131072;        // 4 stages x 2 splits x 4KB

    const float* __restrict__ fin = fsel ? g_feat1 : g_feat0;
    const __nv_bfloat16* __restrict__ wsrc = g_wOs + (size_t)wsel * 9 * 4 * 2 * 2048;

    const int tid = threadIdx.x, wid = tid >> 5, lid = tid & 31;
    const int bm0 = blockIdx.x * 128;

    if (wid == 0) {
        asm volatile("tcgen05.alloc.cta_group::1.sync.aligned.shared::cta.b32 [%0], %1;"
                     :: "r"(sb + TMEMP), "r"(128u) : "memory");
        asm volatile("tcgen05.relinquish_alloc_permit.cta_group::1.sync.aligned;");
    }
    if (tid < 4) mbar_init(sb + MBAR + 8 * tid, 1);
    // preload all 9 taps' base indices
    for (int t = tid; t < 9 * 128; t += 256) {
        int tap = t >> 7, p = t & 127;
        int m = bm0 + p;
        int b = m >> 12, hw = m & 4095, h = hw >> 6, w = hw & 63;
        int yy = h + tap / 3 - 1, xx = w + tap % 3 - 1;
        ((int*)(smem + SIDX))[t] =
            (yy >= 0 && yy < H_ && xx >= 0 && xx < W_)
                ? (((b << 12) + (yy << 6) + xx) << 8) : -1;
    }
    __syncthreads();
    uint32_t tb;
    asm volatile("ld.shared.b32 %0, [%1];" : "=r"(tb) : "r"(sb + TMEMP));

    const int cl4 = (lid & 15) * 4;
    const int ph  = (lid >> 4);

    for (int ks = 0; ks < 36; ++ks) {
        const int tap = ks >> 2, ch = ks & 3;
        const int buf = ks & 3;
        const int uses = ks >> 2;
        if (uses > 0) mbar_wait(sb + MBAR + 8 * buf, (uses - 1) & 1);

        // B tile (1 float4 per thread per split)
        {
            const char* bsh = (const char*)(wsrc + (size_t)(ks * 2) * 2048);
            ((float4*)(smem + BBASE + (buf * 2 + 0) * NB))[tid] = ((const float4*)bsh)[tid];
            ((float4*)(smem + BBASE + (buf * 2 + 1) * NB))[tid] = ((const float4*)(bsh + NB))[tid];
        }
        // A tile
        {
            char* ah = smem + ABASE + (buf * 2 + 0) * 16384;
            char* al = smem + ABASE + (buf * 2 + 1) * 16384;
            const int co = ch * 64 + cl4;
            const int* sidx = (const int*)(smem + SIDX) + tap * 128;
#pragma unroll
            for (int pass = 0; pass < 8; ++pass) {
                int p = pass * 16 + wid * 2 + ph;
                int base = sidx[p];
                float4 r = make_float4(0.f, 0.f, 0.f, 0.f);
                if (base >= 0) r = *(const float4*)(fin + base + co);
                uint2 hp, lp;
                split2(r.x, r.y, hp.x, lp.x);
                split2(r.z, r.w, hp.y, lp.y);
                uint32_t o  = (uint32_t)(p * 128 + (lid & 15) * 8);
                uint32_t so = o ^ ((o >> 3) & 0x70);
                *(uint2*)(ah + so) = hp;
                *(uint2*)(al + so) = lp;
            }
        }
        asm volatile("fence.proxy.async.shared::cta;" ::: "memory");
        __syncthreads();

        if (tid == 0) {
            asm volatile("tcgen05.fence::after_thread_sync;" ::: "memory");
            const uint64_t DB = (2ull << 61) | (1ull << 46) | (64ull << 32) | (1ull << 16);
            uint64_t adh = DB | (((sb + ABASE + (buf * 2 + 0) * 16384) >> 4) & 0x3FFF);
            uint64_t adl = DB | (((sb + ABASE + (buf * 2 + 1) * 16384) >> 4) & 0x3FFF);
            uint64_t bdh = DB | (((sb + BBASE + (buf * 2 + 0) * NB) >> 4) & 0x3FFF);
            uint64_t bdl = DB | (((sb + BBASE + (buf * 2 + 1) * NB) >> 4) & 0x3FFF);
#pragma unroll
            for (int k4 = 0; k4 < 4; k4++)
                mma_f16_ss(tb, adh + 2 * k4, bdh + 2 * k4, IDESC, (ks | k4) != 0);
#pragma unroll
            for (int k4 = 0; k4 < 4; k4++)
                mma_f16_ss(tb, adh + 2 * k4, bdl + 2 * k4, IDESC, 1);
#pragma unroll
            for (int k4 = 0; k4 < 4; k4++)
                mma_f16_ss(tb, adl + 2 * k4, bdh + 2 * k4, IDESC, 1);
            tc_commit(sb + MBAR + 8 * buf);
        }
    }

    // last commit (ks=35, buf=3, 9th completion -> parity 0) implies all done
    mbar_wait(sb + MBAR + 8 * 3, 0);
    asm volatile("tcgen05.fence::after_thread_sync;" ::: "memory");

    if (tid < 128) {
        int m = bm0 + wid * 32 + lid;
        uint32_t r[32];
        LDTM_X32(r, tb);
        asm volatile("tcgen05.wait::ld.sync.aligned;" ::: "memory");
        if (finalOut) {
            int b = m >> 12, hw = m & 4095;
#pragma unroll
            for (int j = 0; j < 18; j++)
                finalOut[((size_t)(b * 18 + j)) * HW_ + hw] = __uint_as_float(r[j]);
        } else {
#pragma unroll
            for (int k = 0; k < 9; k++)
                make_record(m, k, __uint_as_float(r[2 * k]), __uint_as_float(r[2 * k + 1]));
        }
    }
    __syncthreads();
    if (wid == 0)
        asm volatile("tcgen05.dealloc.cta_group::1.sync.aligned.b32 %0, %1;"
                     :: "r"(tb), "r"(128u));
#endif
}

// ================= deform conv (N=256), 2-deep pipeline =====================
__global__ __launch_bounds__(256)
void defconv_kernel(int fsel, int wsel)
{
#if HAS_TC
    constexpr int NB = 256 * 128;   // 32 KB per split
    constexpr uint32_t IDESC =
        (1u << 4) | (1u << 7) | (1u << 10) | (32u << 17) | (8u << 24);

    extern __shared__ char smem[];
    const uint32_t sb = smem_u32(smem);
    const int TMEMP = 0, MBAR = 16, SIDX = 64, SWT = 64 + 2048;
    const int ABASE = 8192;          // 2 stages x 2 splits x 16KB = 64KB
    const int BBASE = 8192 + 65536;  // 2 stages x 2 splits x 32KB = 128KB

    const float* __restrict__ fin = fsel ? g_feat1 : g_feat0;
    float* __restrict__ fout      = fsel ? g_feat0 : g_feat1;
    const __nv_bfloat16* __restrict__ wsrc = g_wDs + (size_t)wsel * 9 * 4 * 2 * 16384;

    const int tid = threadIdx.x, wid = tid >> 5, lid = tid & 31;
    const int bm0 = blockIdx.x * 128;

    if (wid == 0) {
        asm volatile("tcgen05.alloc.cta_group::1.sync.aligned.shared::cta.b32 [%0], %1;"
                     :: "r"(sb + TMEMP), "r"(512u) : "memory");
        asm volatile("tcgen05.relinquish_alloc_permit.cta_group::1.sync.aligned;");
    }
    if (tid < 2) mbar_init(sb + MBAR + 8 * tid, 1);
    __syncthreads();
    uint32_t tb;
    asm volatile("ld.shared.b32 %0, [%1];" : "=r"(tb) : "r"(sb + TMEMP));

    int use0 = 0, use1 = 0;
    const int cl4 = (lid & 15) * 4;
    const int ph  = (lid >> 4);

    for (int tap = 0; tap < 9; ++tap) {
        if (tid < 128) {
            int m = bm0 + tid;
            ((int4*)(smem + SIDX))[tid]  = g_recIdx[(size_t)m * 9 + tap];
            ((float4*)(smem + SWT))[tid] = g_recW[(size_t)m * 9 + tap];
        }
        __syncthreads();

        for (int ch = 0; ch < 4; ++ch) {
            const int ks = tap * 4 + ch;
            const int buf = ks & 1;
            int& u = buf ? use1 : use0;
            if (u > 0) mbar_wait(sb + MBAR + 8 * buf, (u - 1) & 1);

            {
                const char* bsh = (const char*)(wsrc + (size_t)(ks * 2) * 16384);
                float4* dh = (float4*)(smem + BBASE + (buf * 2 + 0) * NB);
                float4* dl = (float4*)(smem + BBASE + (buf * 2 + 1) * NB);
                const float4* sh = (const float4*)bsh;
                const float4* sl = (const float4*)(bsh + NB);
#pragma unroll
                for (int q0 = 0; q0 < NB / 16; q0 += 256) {
                    dh[q0 + tid] = sh[q0 + tid];
                    dl[q0 + tid] = sl[q0 + tid];
                }
            }
            {
                char* ah = smem + ABASE + (buf * 2 + 0) * 16384;
                char* al = smem + ABASE + (buf * 2 + 1) * 16384;
                const int co = ch * 64 + cl4;
#pragma unroll
                for (int pass = 0; pass < 8; ++pass) {
                    int p = pass * 16 + wid * 2 + ph;
                    int4   ii = ((const int4*)(smem + SIDX))[p];
                    float4 wt = ((const float4*)(smem + SWT))[p];
                    float4 a = *(const float4*)(fin + ii.x + co);
                    float4 b = *(const float4*)(fin + ii.y + co);
                    float4 c = *(const float4*)(fin + ii.z + co);
                    float4 d = *(const float4*)(fin + ii.w + co);
                    float4 r;
                    r.x = wt.x*a.x + wt.y*b.x + wt.z*c.x + wt.w*d.x;
                    r.y = wt.x*a.y + wt.y*b.y + wt.z*c.y + wt.w*d.y;
                    r.z = wt.x*a.z + wt.y*b.z + wt.z*c.z + wt.w*d.z;
                    r.w = wt.x*a.w + wt.y*b.w + wt.z*c.w + wt.w*d.w;
                    uint2 hp, lp;
                    split2(r.x, r.y, hp.x, lp.x);
                    split2(r.z, r.w, hp.y, lp.y);
                    uint32_t o  = (uint32_t)(p * 128 + (lid & 15) * 8);
                    uint32_t so = o ^ ((o >> 3) & 0x70);
                    *(uint2*)(ah + so) = hp;
                    *(uint2*)(al + so) = lp;
                }
            }
            asm volatile("fence.proxy.async.shared::cta;" ::: "memory");
            __syncthreads();

            if (tid == 0) {
                asm volatile("tcgen05.fence::after_thread_sync;" ::: "memory");
                const uint64_t DB = (2ull << 61) | (1ull << 46) | (64ull << 32) | (1ull << 16);
                uint64_t adh = DB | (((sb + ABASE + (buf * 2 + 0) * 16384) >> 4) & 0x3FFF);
                uint64_t adl = DB | (((sb + ABASE + (buf * 2 + 1) * 16384) >> 4) & 0x3FFF);
                uint64_t bdh = DB | (((sb + BBASE + (buf * 2 + 0) * NB) >> 4) & 0x3FFF);
                uint64_t bdl = DB | (((sb + BBASE + (buf * 2 + 1) * NB) >> 4) & 0x3FFF);
#pragma unroll
                for (int k4 = 0; k4 < 4; k4++)
                    mma_f16_ss(tb, adh + 2 * k4, bdh + 2 * k4, IDESC, (ks | k4) != 0);
#pragma unroll
                for (int k4 = 0; k4 < 4; k4++)
                    mma_f16_ss(tb, adh + 2 * k4, bdl + 2 * k4, IDESC, 1);
#pragma unroll
                for (int k4 = 0; k4 < 4; k4++)
                    mma_f16_ss(tb, adl + 2 * k4, bdh + 2 * k4, IDESC, 1);
                tc_commit(sb + MBAR + 8 * buf);
            }
            u++;
        }
    }

    // last commit on buf1 (18th completion -> parity 1) implies all done
    mbar_wait(sb + MBAR + 8, 1);
    asm volatile("tcgen05.fence::after_thread_sync;" ::: "memory");

    if (tid < 128) {
        int m = bm0 + wid * 32 + lid;
#pragma unroll
        for (int nb = 0; nb < 8; nb++) {
            uint32_t r[32];
            LDTM_X32(r, tb + nb * 32);
            asm volatile("tcgen05.wait::ld.sync.aligned;" ::: "memory");
            float4* dst = (float4*)(fout + (size_t)m * 256 + nb * 32);
#pragma unroll
            for (int q = 0; q < 8; q++)
                dst[q] = make_float4(__uint_as_float(r[q*4+0]), __uint_as_float(r[q*4+1]),
                                     __uint_as_float(r[q*4+2]), __uint_as_float(r[q*4+3]));
        }
    }
    __syncthreads();
    if (wid == 0)
        asm volatile("tcgen05.dealloc.cta_group::1.sync.aligned.b32 %0, %1;"
                     :: "r"(tb), "r"(512u));
#endif
}

// ---------------------------------------------------------------------------
extern "C" void kernel_launch(void* const* d_in, const int* in_sizes, int n_in,
                              void* d_out, int out_size)
{
    (void)in_sizes; (void)n_in; (void)out_size;
    const float* x  = (const float*)d_in[0];
    const float* y  = (const float*)d_in[1];
    const float* oW = (const float*)d_in[2];
    const float* dW = (const float*)d_in[3];
    float* out = (float*)d_out;

    const int SMEM_D = 8192 + 65536 + 131072;   // 204800
    const int SMEM_O = 8192 + 131072 + 32768;   // 172032
    cudaFuncSetAttribute(defconv_kernel, cudaFuncAttributeMaxDynamicSharedMemorySize, SMEM_D);
    cudaFuncSetAttribute(offconv_kernel, cudaFuncAttributeMaxDynamicSharedMemorySize, SMEM_O);

    dim3 pb(32, 8), pg(HW_ / 32, C_ / 32, B_);
    pack_kernel<<<pg, pb>>>(x, y);

    const int G = 3 * 9 * 4 * 2048 + 4 * 9 * 4 * 256;
    wsplit_kernel<<<(G + 255) / 256, 256>>>(oW, dW);

    int fsel = 0;
    for (int it = 0; it < 3; ++it) {
        offconv_kernel<<<128, 256, SMEM_O>>>(fsel, it, nullptr);
        defconv_kernel<<<128, 256, SMEM_D>>>(fsel, it);
        fsel ^= 1;
    }
    offconv_kernel<<<128, 256, SMEM_O>>>(fsel, 3, out);
}

// round 14
// speedup vs baseline: 1.4363x; 1.4138x over previous
#include <cuda_runtime.h>
#include <cuda_bf16.h>
#include <cstdint>

#if defined(__CUDA_ARCH__) && (defined(__CUDA_ARCH_FEAT_SM103_ALL) || defined(__CUDA_ARCH_SPECIFIC__) || defined(__CUDA_ARCH_FAMILY_SPECIFIC__))
#define HAS_TC 1
#else
#define HAS_TC 0
#endif

static constexpr int B_  = 4;
static constexpr int H_  = 64;
static constexpr int W_  = 64;
static constexpr int C_  = 256;
static constexpr int HW_ = H_ * W_;   // 4096
static constexpr int M_  = B_ * HW_;  // 16384

// ---------------- device scratch -------------------------------------------
__device__ float  g_feat0[(size_t)M_ * C_];
__device__ float  g_feat1[(size_t)M_ * C_];
__device__ int4   g_recIdx[(size_t)M_ * 9];
__device__ float4 g_recW[(size_t)M_ * 9];
__device__ __nv_bfloat16 g_wDs[(size_t)3 * 9 * 4 * 2 * 256 * 64];
__device__ __nv_bfloat16 g_wOs[(size_t)4 * 9 * 4 * 2 * 32 * 64];

// ---------------- PTX helpers ----------------------------------------------
__device__ __forceinline__ uint32_t smem_u32(const void* p) {
    uint32_t a;
    asm("{ .reg .u64 t; cvta.to.shared.u64 t, %1; cvt.u32.u64 %0, t; }" : "=r"(a) : "l"(p));
    return a;
}
#if HAS_TC
__device__ __forceinline__ void mbar_init(uint32_t a, uint32_t cnt) {
    asm volatile("mbarrier.init.shared.b64 [%0], %1;" :: "r"(a), "r"(cnt) : "memory");
}
__device__ __forceinline__ void mbar_wait(uint32_t a, uint32_t phase) {
    asm volatile(
        "{\n\t.reg .pred P;\n\t"
        "WL_%=:\n\t"
        "mbarrier.try_wait.parity.acquire.cta.shared::cta.b64 P, [%0], %1, 0x989680;\n\t"
        "@P bra.uni WD_%=;\n\t"
        "bra.uni WL_%=;\n\t"
        "WD_%=:\n\t}"
        :: "r"(a), "r"(phase) : "memory");
}
__device__ __forceinline__ void mbar_expect_tx(uint32_t a, uint32_t bytes) {
    asm volatile("mbarrier.arrive.expect_tx.shared.b64 _, [%0], %1;"
                 :: "r"(a), "r"(bytes) : "memory");
}
__device__ __forceinline__ void bulk_g2s(uint32_t dst, const void* src,
                                         uint32_t bytes, uint32_t mbar) {
    asm volatile(
        "cp.async.bulk.shared::cta.global.mbarrier::complete_tx::bytes [%0], [%1], %2, [%3];"
        :: "r"(dst), "l"(src), "r"(bytes), "r"(mbar) : "memory");
}
__device__ __forceinline__ void tc_commit(uint32_t mbar) {
    asm volatile(
        "tcgen05.commit.cta_group::1.mbarrier::arrive::one.shared::cluster.b64 [%0];"
        :: "r"(mbar) : "memory");
}
__device__ __forceinline__ void mma_f16_ss(uint32_t d, uint64_t ad, uint64_t bd,
                                           uint32_t idesc, uint32_t en) {
    asm volatile(
        "{\n\t.reg .pred p;\n\t"
        "setp.ne.u32 p, %4, 0;\n\t"
        "tcgen05.mma.cta_group::1.kind::f16 [%0], %1, %2, %3, {%5,%5,%5,%5}, p;\n\t}"
        :: "r"(d), "l"(ad), "l"(bd), "r"(idesc), "r"(en), "r"(0u) : "memory");
}
__device__ __forceinline__ void split2(float a, float b, uint32_t& hp, uint32_t& lp) {
    asm("cvt.rn.bf16x2.f32 %0, %1, %2;" : "=r"(hp) : "f"(b), "f"(a));
    float fa = __uint_as_float(hp << 16);
    float fb = __uint_as_float(hp & 0xFFFF0000u);
    float la = a - fa, lb = b - fb;
    asm("cvt.rn.bf16x2.f32 %0, %1, %2;" : "=r"(lp) : "f"(lb), "f"(la));
}
#define LDTM_X32(r, addr) \
    asm volatile( \
        "tcgen05.ld.sync.aligned.32x32b.x32.b32 " \
        "{%0,%1,%2,%3,%4,%5,%6,%7,%8,%9,%10,%11,%12,%13,%14,%15," \
        "%16,%17,%18,%19,%20,%21,%22,%23,%24,%25,%26,%27,%28,%29,%30,%31}, [%32];" \
        : "=r"((r)[0]),"=r"((r)[1]),"=r"((r)[2]),"=r"((r)[3]), \
          "=r"((r)[4]),"=r"((r)[5]),"=r"((r)[6]),"=r"((r)[7]), \
          "=r"((r)[8]),"=r"((r)[9]),"=r"((r)[10]),"=r"((r)[11]), \
          "=r"((r)[12]),"=r"((r)[13]),"=r"((r)[14]),"=r"((r)[15]), \
          "=r"((r)[16]),"=r"((r)[17]),"=r"((r)[18]),"=r"((r)[19]), \
          "=r"((r)[20]),"=r"((r)[21]),"=r"((r)[22]),"=r"((r)[23]), \
          "=r"((r)[24]),"=r"((r)[25]),"=r"((r)[26]),"=r"((r)[27]), \
          "=r"((r)[28]),"=r"((r)[29]),"=r"((r)[30]),"=r"((r)[31]) \
        : "r"(addr))
#endif

// ---------------- pack: NCHW x,y -> NHWC concat feat0 ----------------------
__global__ void pack_kernel(const float* __restrict__ x, const float* __restrict__ y)
{
    __shared__ float t[32][33];
    int b = blockIdx.z, hw0 = blockIdx.x * 32, c0 = blockIdx.y * 32;
    int tx = threadIdx.x, ty = threadIdx.y;
#pragma unroll
    for (int i = 0; i < 32; i += 8) {
        int c = c0 + ty + i;
        const float* s = (c < 128) ? (x + ((size_t)b * 128 + c) * HW_)
                                   : (y + ((size_t)b * 128 + (c - 128)) * HW_);
        t[ty + i][tx] = s[hw0 + tx];
    }
    __syncthreads();
#pragma unroll
    for (int i = 0; i < 32; i += 8)
        g_feat0[((size_t)b * HW_ + hw0 + ty + i) * C_ + c0 + tx] = t[tx][ty + i];
}

// ---------------- weight split + pre-swizzle --------------------------------
__global__ void wsplit_kernel(const float* __restrict__ oW, const float* __restrict__ dW)
{
#if HAS_TC
    const int GD = 3 * 9 * 4 * 2048;
    const int GO = 4 * 9 * 4 * 256;
    int g = blockIdx.x * blockDim.x + threadIdx.x;
    if (g >= GD + GO) return;
    if (g < GD) {
        int t = g >> 11, o = g & 2047;
        int chunk = t & 3, tap = (t >> 2) % 9, it = (t >> 2) / 9;
        uint32_t boff = (uint32_t)o * 16;
        uint32_t un = boff ^ ((boff >> 3) & 0x70);
        int n = un >> 7, k0 = (un & 127) >> 1;
        uint32_t hp[4], lp[4];
#pragma unroll
        for (int j2 = 0; j2 < 4; j2++) {
            float v0 = dW[((size_t)(it * 256 + n) * 256 + (size_t)(chunk * 64 + k0 + j2 * 2)) * 9 + tap];
            float v1 = dW[((size_t)(it * 256 + n) * 256 + (size_t)(chunk * 64 + k0 + j2 * 2 + 1)) * 9 + tap];
            split2(v0, v1, hp[j2], lp[j2]);
        }
        char* base = (char*)(g_wDs + (size_t)(((it * 9 + tap) * 4 + chunk) * 2) * 16384);
        *(uint4*)(base + boff)         = make_uint4(hp[0], hp[1], hp[2], hp[3]);
        *(uint4*)(base + 32768 + boff) = make_uint4(lp[0], lp[1], lp[2], lp[3]);
    } else {
        int g2 = g - GD;
        int t = g2 >> 8, o = g2 & 255;
        int chunk = t & 3, tap = (t >> 2) % 9, it = (t >> 2) / 9;
        uint32_t boff = (uint32_t)o * 16;
        uint32_t un = boff ^ ((boff >> 3) & 0x70);
        int n = un >> 7, k0 = (un & 127) >> 1;
        uint32_t hp[4], lp[4];
#pragma unroll
        for (int j2 = 0; j2 < 4; j2++) {
            float v0 = (n < 18) ? oW[((size_t)(it * 18 + n) * 256 + (size_t)(chunk * 64 + k0 + j2 * 2)) * 9 + tap] : 0.f;
            float v1 = (n < 18) ? oW[((size_t)(it * 18 + n) * 256 + (size_t)(chunk * 64 + k0 + j2 * 2 + 1)) * 9 + tap] : 0.f;
            split2(v0, v1, hp[j2], lp[j2]);
        }
        char* base = (char*)(g_wOs + (size_t)(((it * 9 + tap) * 4 + chunk) * 2) * 2048);
        *(uint4*)(base + boff)        = make_uint4(hp[0], hp[1], hp[2], hp[3]);
        *(uint4*)(base + 4096 + boff) = make_uint4(lp[0], lp[1], lp[2], lp[3]);
    }
#endif
}

#if HAS_TC
__device__ __forceinline__ void make_record(int m, int k, float dy, float dx)
{
    int b = m >> 12, hw = m & 4095, h = hw >> 6, w = hw & 63;
    float py = dy + (float)(k / 3 - 1) + (float)h;
    float px = dx + (float)(k % 3 - 1) + (float)w;
    float y0f = floorf(py), x0f = floorf(px);
    float wy1 = py - y0f, wy0 = 1.f - wy1;
    float wx1 = px - x0f, wx0 = 1.f - wx1;
    int y0 = (int)y0f, x0 = (int)x0f, y1 = y0 + 1, x1 = x0 + 1;
    int4 ii; float4 ww;
    {
        bool v = (y0 >= 0 && y0 < H_ && x0 >= 0 && x0 < W_);
        int yc = min(max(y0,0),H_-1), xc = min(max(x0,0),W_-1);
        ii.x = ((b << 12) + (yc << 6) + xc) << 8;  ww.x = v ? wy0 * wx0 : 0.f;
    }
    {
        bool v = (y0 >= 0 && y0 < H_ && x1 >= 0 && x1 < W_);
        int yc = min(max(y0,0),H_-1), xc = min(max(x1,0),W_-1);
        ii.y = ((b << 12) + (yc << 6) + xc) << 8;  ww.y = v ? wy0 * wx1 : 0.f;
    }
    {
        bool v = (y1 >= 0 && y1 < H_ && x0 >= 0 && x0 < W_);
        int yc = min(max(y1,0),H_-1), xc = min(max(x0,0),W_-1);
        ii.z = ((b << 12) + (yc << 6) + xc) << 8;  ww.z = v ? wy1 * wx0 : 0.f;
    }
    {
        bool v = (y1 >= 0 && y1 < H_ && x1 >= 0 && x1 < W_);
        int yc = min(max(y1,0),H_-1), xc = min(max(x1,0),W_-1);
        ii.w = ((b << 12) + (yc << 6) + xc) << 8;  ww.w = v ? wy1 * wx1 : 0.f;
    }
    g_recIdx[(size_t)m * 9 + k] = ii;
    g_recW[(size_t)m * 9 + k]   = ww;
}
#endif

// ================= offset conv (N=32), 4-deep ring, fused coords ===========
__global__ __launch_bounds__(256, 1)
void offconv_kernel(int fsel, int wsel, float* __restrict__ finalOut)
{
#if HAS_TC
    constexpr int NB = 32 * 128;   // 4 KB per split
    constexpr uint32_t IDESC =
        (1u << 4) | (1u << 7) | (1u << 10) | (4u << 17) | (8u << 24);

    extern __shared__ char smem[];
    const uint32_t sb = smem_u32(smem);
    const int TMEMP = 0, MB_MMA = 16, MB_B = 48, SIDX = 128;
    const int ABASE = 16384;                  // 4 stages x 2 splits x 16KB = 128KB
    const int BBASE = 16384 + 131072;         // 4 stages x 2 splits x 4KB  = 32KB

    const float* __restrict__ fin = fsel ? g_feat1 : g_feat0;
    const __nv_bfloat16* __restrict__ wsrc = g_wOs + (size_t)wsel * 9 * 4 * 2 * 2048;

    const int tid = threadIdx.x, wid = tid >> 5, lid = tid & 31;
    const int bm0 = blockIdx.x * 128;

    if (wid == 0) {
        asm volatile("tcgen05.alloc.cta_group::1.sync.aligned.shared::cta.b32 [%0], %1;"
                     :: "r"(sb + TMEMP), "r"(128u) : "memory");
        asm volatile("tcgen05.relinquish_alloc_permit.cta_group::1.sync.aligned;");
    }
    if (tid < 4) { mbar_init(sb + MB_MMA + 8 * tid, 1); mbar_init(sb + MB_B + 8 * tid, 1); }
    for (int t = tid; t < 9 * 128; t += 256) {
        int tap = t >> 7, p = t & 127;
        int m = bm0 + p;
        int b = m >> 12, hw = m & 4095, h = hw >> 6, w = hw & 63;
        int yy = h + tap / 3 - 1, xx = w + tap % 3 - 1;
        ((int*)(smem + SIDX))[t] =
            (yy >= 0 && yy < H_ && xx >= 0 && xx < W_)
                ? (((b << 12) + (yy << 6) + xx) << 8) : -1;
    }
    __syncthreads();
    uint32_t tb;
    asm volatile("ld.shared.b32 %0, [%1];" : "=r"(tb) : "r"(sb + TMEMP));

    const int cl4 = (lid & 15) * 4;
    const int ph  = (lid >> 4);

    for (int ks = 0; ks < 36; ++ks) {
        const int tap = ks >> 2, ch = ks & 3;
        const int buf = ks & 3;
        const int u = ks >> 2;
        if (u > 0) mbar_wait(sb + MB_MMA + 8 * buf, (u - 1) & 1);

        if (tid == 0) {
            mbar_expect_tx(sb + MB_B + 8 * buf, 2 * NB);
            bulk_g2s(sb + BBASE + (buf * 2 + 0) * NB,
                     (const char*)wsrc + (size_t)(ks * 2) * 4096, NB, sb + MB_B + 8 * buf);
            bulk_g2s(sb + BBASE + (buf * 2 + 1) * NB,
                     (const char*)wsrc + (size_t)(ks * 2) * 4096 + NB, NB, sb + MB_B + 8 * buf);
        }
        // A tile: 2 pixels per group, loads hoisted
        {
            char* ah = smem + ABASE + (buf * 2 + 0) * 16384;
            char* al = smem + ABASE + (buf * 2 + 1) * 16384;
            const int co = ch * 64 + cl4;
            const int* sidx = (const int*)(smem + SIDX) + tap * 128;
#pragma unroll
            for (int g = 0; g < 4; ++g) {
                int p0 = (2 * g) * 16 + wid * 2 + ph, p1 = p0 + 16;
                int b0 = sidx[p0], b1 = sidx[p1];
                float4 r0 = make_float4(0.f,0.f,0.f,0.f), r1 = r0;
                if (b0 >= 0) r0 = __ldg((const float4*)(fin + b0 + co));
                if (b1 >= 0) r1 = __ldg((const float4*)(fin + b1 + co));
                uint2 hp0, lp0, hp1, lp1;
                split2(r0.x, r0.y, hp0.x, lp0.x);
                split2(r0.z, r0.w, hp0.y, lp0.y);
                split2(r1.x, r1.y, hp1.x, lp1.x);
                split2(r1.z, r1.w, hp1.y, lp1.y);
                uint32_t o0 = (uint32_t)(p0 * 128 + (lid & 15) * 8);
                uint32_t o1 = (uint32_t)(p1 * 128 + (lid & 15) * 8);
                uint32_t s0 = o0 ^ ((o0 >> 3) & 0x70);
                uint32_t s1 = o1 ^ ((o1 >> 3) & 0x70);
                *(uint2*)(ah + s0) = hp0; *(uint2*)(al + s0) = lp0;
                *(uint2*)(ah + s1) = hp1; *(uint2*)(al + s1) = lp1;
            }
        }
        asm volatile("fence.proxy.async.shared::cta;" ::: "memory");
        __syncthreads();

        if (tid == 0) {
            mbar_wait(sb + MB_B + 8 * buf, u & 1);
            asm volatile("tcgen05.fence::after_thread_sync;" ::: "memory");
            const uint64_t DB = (2ull << 61) | (1ull << 46) | (64ull << 32) | (1ull << 16);
            uint64_t adh = DB | (((sb + ABASE + (buf * 2 + 0) * 16384) >> 4) & 0x3FFF);
            uint64_t adl = DB | (((sb + ABASE + (buf * 2 + 1) * 16384) >> 4) & 0x3FFF);
            uint64_t bdh = DB | (((sb + BBASE + (buf * 2 + 0) * NB) >> 4) & 0x3FFF);
            uint64_t bdl = DB | (((sb + BBASE + (buf * 2 + 1) * NB) >> 4) & 0x3FFF);
#pragma unroll
            for (int k4 = 0; k4 < 4; k4++)
                mma_f16_ss(tb, adh + 2 * k4, bdh + 2 * k4, IDESC, (ks | k4) != 0);
#pragma unroll
            for (int k4 = 0; k4 < 4; k4++)
                mma_f16_ss(tb, adh + 2 * k4, bdl + 2 * k4, IDESC, 1);
#pragma unroll
            for (int k4 = 0; k4 < 4; k4++)
                mma_f16_ss(tb, adl + 2 * k4, bdh + 2 * k4, IDESC, 1);
            tc_commit(sb + MB_MMA + 8 * buf);
        }
    }

    mbar_wait(sb + MB_MMA + 8 * 3, 0);   // buf3 9th completion -> parity 0
    asm volatile("tcgen05.fence::after_thread_sync;" ::: "memory");

    if (tid < 128) {
        int m = bm0 + wid * 32 + lid;
        uint32_t r[32];
        LDTM_X32(r, tb);
        asm volatile("tcgen05.wait::ld.sync.aligned;" ::: "memory");
        if (finalOut) {
            int b = m >> 12, hw = m & 4095;
#pragma unroll
            for (int j = 0; j < 18; j++)
                finalOut[((size_t)(b * 18 + j)) * HW_ + hw] = __uint_as_float(r[j]);
        } else {
#pragma unroll
            for (int k = 0; k < 9; k++)
                make_record(m, k, __uint_as_float(r[2 * k]), __uint_as_float(r[2 * k + 1]));
        }
    }
    __syncthreads();
    if (wid == 0)
        asm volatile("tcgen05.dealloc.cta_group::1.sync.aligned.b32 %0, %1;"
                     :: "r"(tb), "r"(128u));
#endif
}

// ================= deform conv (N=256), 2-deep ring, bulk B ================
__global__ __launch_bounds__(256, 1)
void defconv_kernel(int fsel, int wsel)
{
#if HAS_TC
    constexpr int NB = 256 * 128;   // 32 KB per split
    constexpr uint32_t IDESC =
        (1u << 4) | (1u << 7) | (1u << 10) | (32u << 17) | (8u << 24);

    extern __shared__ char smem[];
    const uint32_t sb = smem_u32(smem);
    const int TMEMP = 0, MB_MMA = 16, MB_B = 32;
    const int SIDX = 64;            // 2 regions x 2048
    const int SWT  = 64 + 4096;     // 2 regions x 2048
    const int ABASE = 16384;        // 2 stages x 2 splits x 16KB = 64KB
    const int BBASE = 16384 + 65536;// 2 stages x 2 splits x 32KB = 128KB -> ends 212992

    const float* __restrict__ fin = fsel ? g_feat1 : g_feat0;
    float* __restrict__ fout      = fsel ? g_feat0 : g_feat1;
    const __nv_bfloat16* __restrict__ wsrc = g_wDs + (size_t)wsel * 9 * 4 * 2 * 16384;

    const int tid = threadIdx.x, wid = tid >> 5, lid = tid & 31;
    const int bm0 = blockIdx.x * 128;

    if (wid == 0) {
        asm volatile("tcgen05.alloc.cta_group::1.sync.aligned.shared::cta.b32 [%0], %1;"
                     :: "r"(sb + TMEMP), "r"(512u) : "memory");
        asm volatile("tcgen05.relinquish_alloc_permit.cta_group::1.sync.aligned;");
    }
    if (tid < 2) { mbar_init(sb + MB_MMA + 8 * tid, 1); mbar_init(sb + MB_B + 8 * tid, 1); }
    // stage tap 0 records into region 0
    if (tid < 128) {
        int m = bm0 + tid;
        ((int4*)(smem + SIDX))[tid]  = g_recIdx[(size_t)m * 9];
        ((float4*)(smem + SWT))[tid] = g_recW[(size_t)m * 9];
    }
    __syncthreads();
    uint32_t tb;
    asm volatile("ld.shared.b32 %0, [%1];" : "=r"(tb) : "r"(sb + TMEMP));

    const int cl4 = (lid & 15) * 4;
    const int ph  = (lid >> 4);

    for (int ks = 0; ks < 36; ++ks) {
        const int tap = ks >> 2, ch = ks & 3;
        const int buf = ks & 1;
        const int u = ks >> 1;
        if (u > 0) mbar_wait(sb + MB_MMA + 8 * buf, (u - 1) & 1);

        if (tid == 0) {
            mbar_expect_tx(sb + MB_B + 8 * buf, 2 * NB);
            bulk_g2s(sb + BBASE + (buf * 2 + 0) * NB,
                     (const char*)wsrc + (size_t)(ks * 2) * 32768, NB, sb + MB_B + 8 * buf);
            bulk_g2s(sb + BBASE + (buf * 2 + 1) * NB,
                     (const char*)wsrc + (size_t)(ks * 2) * 32768 + NB, NB, sb + MB_B + 8 * buf);
        }
        // prefetch next tap's records during first chunk of current tap
        if (ch == 0 && tap + 1 < 9 && tid < 128) {
            int m = bm0 + tid;
            int r = (tap + 1) & 1;
            ((int4*)(smem + SIDX + r * 2048))[tid]  = g_recIdx[(size_t)m * 9 + tap + 1];
            ((float4*)(smem + SWT + r * 2048))[tid] = g_recW[(size_t)m * 9 + tap + 1];
        }
        // A tile: gather + blend + split, 2 pixels per group with loads hoisted
        {
            char* ah = smem + ABASE + (buf * 2 + 0) * 16384;
            char* al = smem + ABASE + (buf * 2 + 1) * 16384;
            const int co = ch * 64 + cl4;
            const int4*   sI = (const int4*)(smem + SIDX + (tap & 1) * 2048);
            const float4* sW = (const float4*)(smem + SWT + (tap & 1) * 2048);
#pragma unroll
            for (int g = 0; g < 4; ++g) {
                int p0 = (2 * g) * 16 + wid * 2 + ph, p1 = p0 + 16;
                int4   i0 = sI[p0], i1 = sI[p1];
                float4 w0 = sW[p0], w1 = sW[p1];
                float4 a0 = __ldg((const float4*)(fin + i0.x + co));
                float4 b0 = __ldg((const float4*)(fin + i0.y + co));
                float4 c0 = __ldg((const float4*)(fin + i0.z + co));
                float4 d0 = __ldg((const float4*)(fin + i0.w + co));
                float4 a1 = __ldg((const float4*)(fin + i1.x + co));
                float4 b1 = __ldg((const float4*)(fin + i1.y + co));
                float4 c1 = __ldg((const float4*)(fin + i1.z + co));
                float4 d1 = __ldg((const float4*)(fin + i1.w + co));
                float4 r0, r1;
                r0.x = w0.x*a0.x + w0.y*b0.x + w0.z*c0.x + w0.w*d0.x;
                r0.y = w0.x*a0.y + w0.y*b0.y + w0.z*c0.y + w0.w*d0.y;
                r0.z = w0.x*a0.z + w0.y*b0.z + w0.z*c0.z + w0.w*d0.z;
                r0.w = w0.x*a0.w + w0.y*b0.w + w0.z*c0.w + w0.w*d0.w;
                r1.x = w1.x*a1.x + w1.y*b1.x + w1.z*c1.x + w1.w*d1.x;
                r1.y = w1.x*a1.y + w1.y*b1.y + w1.z*c1.y + w1.w*d1.y;
                r1.z = w1.x*a1.z + w1.y*b1.z + w1.z*c1.z + w1.w*d1.z;
                r1.w = w1.x*a1.w + w1.y*b1.w + w1.z*c1.w + w1.w*d1.w;
                uint2 hp0, lp0, hp1, lp1;
                split2(r0.x, r0.y, hp0.x, lp0.x);
                split2(r0.z, r0.w, hp0.y, lp0.y);
                split2(r1.x, r1.y, hp1.x, lp1.x);
                split2(r1.z, r1.w, hp1.y, lp1.y);
                uint32_t o0 = (uint32_t)(p0 * 128 + (lid & 15) * 8);
                uint32_t o1 = (uint32_t)(p1 * 128 + (lid & 15) * 8);
                uint32_t s0 = o0 ^ ((o0 >> 3) & 0x70);
                uint32_t s1 = o1 ^ ((o1 >> 3) & 0x70);
                *(uint2*)(ah + s0) = hp0; *(uint2*)(al + s0) = lp0;
                *(uint2*)(ah + s1) = hp1; *(uint2*)(al + s1) = lp1;
            }
        }
        asm volatile("fence.proxy.async.shared::cta;" ::: "memory");
        __syncthreads();

        if (tid == 0) {
            mbar_wait(sb + MB_B + 8 * buf, u & 1);
            asm volatile("tcgen05.fence::after_thread_sync;" ::: "memory");
            const uint64_t DB = (2ull << 61) | (1ull << 46) | (64ull << 32) | (1ull << 16);
            uint64_t adh = DB | (((sb + ABASE + (buf * 2 + 0) * 16384) >> 4) & 0x3FFF);
            uint64_t adl = DB | (((sb + ABASE + (buf * 2 + 1) * 16384) >> 4) & 0x3FFF);
            uint64_t bdh = DB | (((sb + BBASE + (buf * 2 + 0) * NB) >> 4) & 0x3FFF);
            uint64_t bdl = DB | (((sb + BBASE + (buf * 2 + 1) * NB) >> 4) & 0x3FFF);
#pragma unroll
            for (int k4 = 0; k4 < 4; k4++)
                mma_f16_ss(tb, adh + 2 * k4, bdh + 2 * k4, IDESC, (ks | k4) != 0);
#pragma unroll
            for (int k4 = 0; k4 < 4; k4++)
                mma_f16_ss(tb, adh + 2 * k4, bdl + 2 * k4, IDESC, 1);
#pragma unroll
            for (int k4 = 0; k4 < 4; k4++)
                mma_f16_ss(tb, adl + 2 * k4, bdh + 2 * k4, IDESC, 1);
            tc_commit(sb + MB_MMA + 8 * buf);
        }
    }

    mbar_wait(sb + MB_MMA + 8, 1);   // buf1 18th completion -> parity 1
    asm volatile("tcgen05.fence::after_thread_sync;" ::: "memory");

    if (tid < 128) {
        int m = bm0 + wid * 32 + lid;
#pragma unroll
        for (int nb = 0; nb < 8; nb++) {
            uint32_t r[32];
            LDTM_X32(r, tb + nb * 32);
            asm volatile("tcgen05.wait::ld.sync.aligned;" ::: "memory");
            float4* dst = (float4*)(fout + (size_t)m * 256 + nb * 32);
#pragma unroll
            for (int q = 0; q < 8; q++)
                dst[q] = make_float4(__uint_as_float(r[q*4+0]), __uint_as_float(r[q*4+1]),
                                     __uint_as_float(r[q*4+2]), __uint_as_float(r[q*4+3]));
        }
    }
    __syncthreads();
    if (wid == 0)
        asm volatile("tcgen05.dealloc.cta_group::1.sync.aligned.b32 %0, %1;"
                     :: "r"(tb), "r"(512u));
#endif
}

// ---------------------------------------------------------------------------
extern "C" void kernel_launch(void* const* d_in, const int* in_sizes, int n_in,
                              void* d_out, int out_size)
{
    (void)in_sizes; (void)n_in; (void)out_size;
    const float* x  = (const float*)d_in[0];
    const float* y  = (const float*)d_in[1];
    const float* oW = (const float*)d_in[2];
    const float* dW = (const float*)d_in[3];
    float* out = (float*)d_out;

    const int SMEM_D = 16384 + 65536 + 131072;   // 212992
    const int SMEM_O = 16384 + 131072 + 32768;   // 180224
    cudaFuncSetAttribute(defconv_kernel, cudaFuncAttributeMaxDynamicSharedMemorySize, SMEM_D);
    cudaFuncSetAttribute(offconv_kernel, cudaFuncAttributeMaxDynamicSharedMemorySize, SMEM_O);

    dim3 pb(32, 8), pg(HW_ / 32, C_ / 32, B_);
    pack_kernel<<<pg, pb>>>(x, y);

    const int G = 3 * 9 * 4 * 2048 + 4 * 9 * 4 * 256;
    wsplit_kernel<<<(G + 255) / 256, 256>>>(oW, dW);

    int fsel = 0;
    for (int it = 0; it < 3; ++it) {
        offconv_kernel<<<128, 256, SMEM_O>>>(fsel, it, nullptr);
        defconv_kernel<<<128, 256, SMEM_D>>>(fsel, it);
        fsel ^= 1;
    }
    offconv_kernel<<<128, 256, SMEM_O>>>(fsel, 3, out);
}

// round 15
// speedup vs baseline: 1.4364x; 1.0001x over previous
#include <cuda_runtime.h>
#include <cuda_bf16.h>
#include <cstdint>

#if defined(__CUDA_ARCH__) && (defined(__CUDA_ARCH_FEAT_SM103_ALL) || defined(__CUDA_ARCH_SPECIFIC__) || defined(__CUDA_ARCH_FAMILY_SPECIFIC__))
#define HAS_TC 1
#else
#define HAS_TC 0
#endif

static constexpr int B_  = 4;
static constexpr int H_  = 64;
static constexpr int W_  = 64;
static constexpr int C_  = 256;
static constexpr int HW_ = H_ * W_;   // 4096
static constexpr int M_  = B_ * HW_;  // 16384

// ---------------- device scratch -------------------------------------------
__device__ float  g_feat0[(size_t)M_ * C_];
__device__ float  g_feat1[(size_t)M_ * C_];
__device__ int4   g_recIdx[(size_t)M_ * 9];
__device__ float4 g_recW[(size_t)M_ * 9];
__device__ __nv_bfloat16 g_wDs[(size_t)3 * 9 * 4 * 2 * 256 * 64];
__device__ __nv_bfloat16 g_wOs[(size_t)4 * 9 * 4 * 2 * 32 * 64];

// ---------------- PTX helpers ----------------------------------------------
__device__ __forceinline__ uint32_t smem_u32(const void* p) {
    uint32_t a;
    asm("{ .reg .u64 t; cvta.to.shared.u64 t, %1; cvt.u32.u64 %0, t; }" : "=r"(a) : "l"(p));
    return a;
}
#if HAS_TC
__device__ __forceinline__ void mbar_init(uint32_t a, uint32_t cnt) {
    asm volatile("mbarrier.init.shared.b64 [%0], %1;" :: "r"(a), "r"(cnt) : "memory");
}
__device__ __forceinline__ void mbar_wait(uint32_t a, uint32_t phase) {
    asm volatile(
        "{\n\t.reg .pred P;\n\t"
        "WL_%=:\n\t"
        "mbarrier.try_wait.parity.acquire.cta.shared::cta.b64 P, [%0], %1, 0x989680;\n\t"
        "@P bra.uni WD_%=;\n\t"
        "bra.uni WL_%=;\n\t"
        "WD_%=:\n\t}"
        :: "r"(a), "r"(phase) : "memory");
}
__device__ __forceinline__ void mbar_expect_tx(uint32_t a, uint32_t bytes) {
    asm volatile("mbarrier.arrive.expect_tx.shared.b64 _, [%0], %1;"
                 :: "r"(a), "r"(bytes) : "memory");
}
__device__ __forceinline__ void bulk_g2s(uint32_t dst, const void* src,
                                         uint32_t bytes, uint32_t mbar) {
    asm volatile(
        "cp.async.bulk.shared::cta.global.mbarrier::complete_tx::bytes [%0], [%1], %2, [%3];"
        :: "r"(dst), "l"(src), "r"(bytes), "r"(mbar) : "memory");
}
__device__ __forceinline__ void tc_commit(uint32_t mbar) {
    asm volatile(
        "tcgen05.commit.cta_group::1.mbarrier::arrive::one.shared::cluster.b64 [%0];"
        :: "r"(mbar) : "memory");
}
__device__ __forceinline__ void mma_f16_ss(uint32_t d, uint64_t ad, uint64_t bd,
                                           uint32_t idesc, uint32_t en) {
    asm volatile(
        "{\n\t.reg .pred p;\n\t"
        "setp.ne.u32 p, %4, 0;\n\t"
        "tcgen05.mma.cta_group::1.kind::f16 [%0], %1, %2, %3, {%5,%5,%5,%5}, p;\n\t}"
        :: "r"(d), "l"(ad), "l"(bd), "r"(idesc), "r"(en), "r"(0u) : "memory");
}
__device__ __forceinline__ void split2(float a, float b, uint32_t& hp, uint32_t& lp) {
    asm("cvt.rn.bf16x2.f32 %0, %1, %2;" : "=r"(hp) : "f"(b), "f"(a));
    float fa = __uint_as_float(hp << 16);
    float fb = __uint_as_float(hp & 0xFFFF0000u);
    float la = a - fa, lb = b - fb;
    asm("cvt.rn.bf16x2.f32 %0, %1, %2;" : "=r"(lp) : "f"(lb), "f"(la));
}
#define LDTM_X32(r, addr) \
    asm volatile( \
        "tcgen05.ld.sync.aligned.32x32b.x32.b32 " \
        "{%0,%1,%2,%3,%4,%5,%6,%7,%8,%9,%10,%11,%12,%13,%14,%15," \
        "%16,%17,%18,%19,%20,%21,%22,%23,%24,%25,%26,%27,%28,%29,%30,%31}, [%32];" \
        : "=r"((r)[0]),"=r"((r)[1]),"=r"((r)[2]),"=r"((r)[3]), \
          "=r"((r)[4]),"=r"((r)[5]),"=r"((r)[6]),"=r"((r)[7]), \
          "=r"((r)[8]),"=r"((r)[9]),"=r"((r)[10]),"=r"((r)[11]), \
          "=r"((r)[12]),"=r"((r)[13]),"=r"((r)[14]),"=r"((r)[15]), \
          "=r"((r)[16]),"=r"((r)[17]),"=r"((r)[18]),"=r"((r)[19]), \
          "=r"((r)[20]),"=r"((r)[21]),"=r"((r)[22]),"=r"((r)[23]), \
          "=r"((r)[24]),"=r"((r)[25]),"=r"((r)[26]),"=r"((r)[27]), \
          "=r"((r)[28]),"=r"((r)[29]),"=r"((r)[30]),"=r"((r)[31]) \
        : "r"(addr))
#endif

// ---------------- pack: NCHW x,y -> NHWC concat feat0 ----------------------
__global__ void pack_kernel(const float* __restrict__ x, const float* __restrict__ y)
{
    __shared__ float t[32][33];
    int b = blockIdx.z, hw0 = blockIdx.x * 32, c0 = blockIdx.y * 32;
    int tx = threadIdx.x, ty = threadIdx.y;
#pragma unroll
    for (int i = 0; i < 32; i += 8) {
        int c = c0 + ty + i;
        const float* s = (c < 128) ? (x + ((size_t)b * 128 + c) * HW_)
                                   : (y + ((size_t)b * 128 + (c - 128)) * HW_);
        t[ty + i][tx] = s[hw0 + tx];
    }
    __syncthreads();
#pragma unroll
    for (int i = 0; i < 32; i += 8)
        g_feat0[((size_t)b * HW_ + hw0 + ty + i) * C_ + c0 + tx] = t[tx][ty + i];
}

// ---------------- weight split + pre-swizzle --------------------------------
__global__ void wsplit_kernel(const float* __restrict__ oW, const float* __restrict__ dW)
{
#if HAS_TC
    const int GD = 3 * 9 * 4 * 2048;
    const int GO = 4 * 9 * 4 * 256;
    int g = blockIdx.x * blockDim.x + threadIdx.x;
    if (g >= GD + GO) return;
    if (g < GD) {
        int t = g >> 11, o = g & 2047;
        int chunk = t & 3, tap = (t >> 2) % 9, it = (t >> 2) / 9;
        uint32_t boff = (uint32_t)o * 16;
        uint32_t un = boff ^ ((boff >> 3) & 0x70);
        int n = un >> 7, k0 = (un & 127) >> 1;
        uint32_t hp[4], lp[4];
#pragma unroll
        for (int j2 = 0; j2 < 4; j2++) {
            float v0 = dW[((size_t)(it * 256 + n) * 256 + (size_t)(chunk * 64 + k0 + j2 * 2)) * 9 + tap];
            float v1 = dW[((size_t)(it * 256 + n) * 256 + (size_t)(chunk * 64 + k0 + j2 * 2 + 1)) * 9 + tap];
            split2(v0, v1, hp[j2], lp[j2]);
        }
        char* base = (char*)(g_wDs + (size_t)(((it * 9 + tap) * 4 + chunk) * 2) * 16384);
        *(uint4*)(base + boff)         = make_uint4(hp[0], hp[1], hp[2], hp[3]);
        *(uint4*)(base + 32768 + boff) = make_uint4(lp[0], lp[1], lp[2], lp[3]);
    } else {
        int g2 = g - GD;
        int t = g2 >> 8, o = g2 & 255;
        int chunk = t & 3, tap = (t >> 2) % 9, it = (t >> 2) / 9;
        uint32_t boff = (uint32_t)o * 16;
        uint32_t un = boff ^ ((boff >> 3) & 0x70);
        int n = un >> 7, k0 = (un & 127) >> 1;
        uint32_t hp[4], lp[4];
#pragma unroll
        for (int j2 = 0; j2 < 4; j2++) {
            float v0 = (n < 18) ? oW[((size_t)(it * 18 + n) * 256 + (size_t)(chunk * 64 + k0 + j2 * 2)) * 9 + tap] : 0.f;
            float v1 = (n < 18) ? oW[((size_t)(it * 18 + n) * 256 + (size_t)(chunk * 64 + k0 + j2 * 2 + 1)) * 9 + tap] : 0.f;
            split2(v0, v1, hp[j2], lp[j2]);
        }
        char* base = (char*)(g_wOs + (size_t)(((it * 9 + tap) * 4 + chunk) * 2) * 2048);
        *(uint4*)(base + boff)        = make_uint4(hp[0], hp[1], hp[2], hp[3]);
        *(uint4*)(base + 4096 + boff) = make_uint4(lp[0], lp[1], lp[2], lp[3]);
    }
#endif
}

#if HAS_TC
__device__ __forceinline__ void make_record(int m, int k, float dy, float dx)
{
    int b = m >> 12, hw = m & 4095, h = hw >> 6, w = hw & 63;
    float py = dy + (float)(k / 3 - 1) + (float)h;
    float px = dx + (float)(k % 3 - 1) + (float)w;
    float y0f = floorf(py), x0f = floorf(px);
    float wy1 = py - y0f, wy0 = 1.f - wy1;
    float wx1 = px - x0f, wx0 = 1.f - wx1;
    int y0 = (int)y0f, x0 = (int)x0f, y1 = y0 + 1, x1 = x0 + 1;
    int4 ii; float4 ww;
    {
        bool v = (y0 >= 0 && y0 < H_ && x0 >= 0 && x0 < W_);
        int yc = min(max(y0,0),H_-1), xc = min(max(x0,0),W_-1);
        ii.x = ((b << 12) + (yc << 6) + xc) << 8;  ww.x = v ? wy0 * wx0 : 0.f;
    }
    {
        bool v = (y0 >= 0 && y0 < H_ && x1 >= 0 && x1 < W_);
        int yc = min(max(y0,0),H_-1), xc = min(max(x1,0),W_-1);
        ii.y = ((b << 12) + (yc << 6) + xc) << 8;  ww.y = v ? wy0 * wx1 : 0.f;
    }
    {
        bool v = (y1 >= 0 && y1 < H_ && x0 >= 0 && x0 < W_);
        int yc = min(max(y1,0),H_-1), xc = min(max(x0,0),W_-1);
        ii.z = ((b << 12) + (yc << 6) + xc) << 8;  ww.z = v ? wy1 * wx0 : 0.f;
    }
    {
        bool v = (y1 >= 0 && y1 < H_ && x1 >= 0 && x1 < W_);
        int yc = min(max(y1,0),H_-1), xc = min(max(x1,0),W_-1);
        ii.w = ((b << 12) + (yc << 6) + xc) << 8;  ww.w = v ? wy1 * wx1 : 0.f;
    }
    g_recIdx[(size_t)m * 9 + k] = ii;
    g_recW[(size_t)m * 9 + k]   = ww;
}
#endif

// ================= offset conv (N=32), 4-deep ring, fused coords ===========
__global__ __launch_bounds__(256, 1)
void offconv_kernel(int fsel, int wsel, float* __restrict__ finalOut)
{
#if HAS_TC
    constexpr int NB = 32 * 128;   // 4 KB per split
    constexpr uint32_t IDESC =
        (1u << 4) | (1u << 7) | (1u << 10) | (4u << 17) | (8u << 24);

    extern __shared__ char smem[];
    const uint32_t sb = smem_u32(smem);
    const int TMEMP = 0, MB_MMA = 16, MB_B = 48, SIDX = 128;
    const int ABASE = 16384;                  // 4 stages x 2 splits x 16KB = 128KB
    const int BBASE = 16384 + 131072;         // 4 stages x 2 splits x 4KB  = 32KB

    const float* __restrict__ fin = fsel ? g_feat1 : g_feat0;
    const __nv_bfloat16* __restrict__ wsrc = g_wOs + (size_t)wsel * 9 * 4 * 2 * 2048;

    const int tid = threadIdx.x, wid = tid >> 5, lid = tid & 31;
    const int bm0 = blockIdx.x * 128;

    if (wid == 0) {
        asm volatile("tcgen05.alloc.cta_group::1.sync.aligned.shared::cta.b32 [%0], %1;"
                     :: "r"(sb + TMEMP), "r"(128u) : "memory");
        asm volatile("tcgen05.relinquish_alloc_permit.cta_group::1.sync.aligned;");
    }
    if (tid < 4) { mbar_init(sb + MB_MMA + 8 * tid, 1); mbar_init(sb + MB_B + 8 * tid, 1); }
    for (int t = tid; t < 9 * 128; t += 256) {
        int tap = t >> 7, p = t & 127;
        int m = bm0 + p;
        int b = m >> 12, hw = m & 4095, h = hw >> 6, w = hw & 63;
        int yy = h + tap / 3 - 1, xx = w + tap % 3 - 1;
        ((int*)(smem + SIDX))[t] =
            (yy >= 0 && yy < H_ && xx >= 0 && xx < W_)
                ? (((b << 12) + (yy << 6) + xx) << 8) : -1;
    }
    __syncthreads();
    uint32_t tb;
    asm volatile("ld.shared.b32 %0, [%1];" : "=r"(tb) : "r"(sb + TMEMP));

    const int cl4 = (lid & 15) * 4;
    const int ph  = (lid >> 4);

    for (int ks = 0; ks < 36; ++ks) {
        const int tap = ks >> 2, ch = ks & 3;
        const int buf = ks & 3;
        const int u = ks >> 2;
        if (u > 0) mbar_wait(sb + MB_MMA + 8 * buf, (u - 1) & 1);

        if (tid == 0) {
            mbar_expect_tx(sb + MB_B + 8 * buf, 2 * NB);
            bulk_g2s(sb + BBASE + (buf * 2 + 0) * NB,
                     (const char*)wsrc + (size_t)(ks * 2) * 4096, NB, sb + MB_B + 8 * buf);
            bulk_g2s(sb + BBASE + (buf * 2 + 1) * NB,
                     (const char*)wsrc + (size_t)(ks * 2) * 4096 + NB, NB, sb + MB_B + 8 * buf);
        }
        // A tile: 2 pixels per group, loads hoisted
        {
            char* ah = smem + ABASE + (buf * 2 + 0) * 16384;
            char* al = smem + ABASE + (buf * 2 + 1) * 16384;
            const int co = ch * 64 + cl4;
            const int* sidx = (const int*)(smem + SIDX) + tap * 128;
#pragma unroll
            for (int g = 0; g < 4; ++g) {
                int p0 = (2 * g) * 16 + wid * 2 + ph, p1 = p0 + 16;
                int b0 = sidx[p0], b1 = sidx[p1];
                float4 r0 = make_float4(0.f,0.f,0.f,0.f), r1 = r0;
                if (b0 >= 0) r0 = __ldg((const float4*)(fin + b0 + co));
                if (b1 >= 0) r1 = __ldg((const float4*)(fin + b1 + co));
                uint2 hp0, lp0, hp1, lp1;
                split2(r0.x, r0.y, hp0.x, lp0.x);
                split2(r0.z, r0.w, hp0.y, lp0.y);
                split2(r1.x, r1.y, hp1.x, lp1.x);
                split2(r1.z, r1.w, hp1.y, lp1.y);
                uint32_t o0 = (uint32_t)(p0 * 128 + (lid & 15) * 8);
                uint32_t o1 = (uint32_t)(p1 * 128 + (lid & 15) * 8);
                uint32_t s0 = o0 ^ ((o0 >> 3) & 0x70);
                uint32_t s1 = o1 ^ ((o1 >> 3) & 0x70);
                *(uint2*)(ah + s0) = hp0; *(uint2*)(al + s0) = lp0;
                *(uint2*)(ah + s1) = hp1; *(uint2*)(al + s1) = lp1;
            }
        }
        asm volatile("fence.proxy.async.shared::cta;" ::: "memory");
        __syncthreads();

        if (tid == 0) {
            mbar_wait(sb + MB_B + 8 * buf, u & 1);
            asm volatile("tcgen05.fence::after_thread_sync;" ::: "memory");
            const uint64_t DB = (2ull << 61) | (1ull << 46) | (64ull << 32) | (1ull << 16);
            uint64_t adh = DB | (((sb + ABASE + (buf * 2 + 0) * 16384) >> 4) & 0x3FFF);
            uint64_t adl = DB | (((sb + ABASE + (buf * 2 + 1) * 16384) >> 4) & 0x3FFF);
            uint64_t bdh = DB | (((sb + BBASE + (buf * 2 + 0) * NB) >> 4) & 0x3FFF);
            uint64_t bdl = DB | (((sb + BBASE + (buf * 2 + 1) * NB) >> 4) & 0x3FFF);
#pragma unroll
            for (int k4 = 0; k4 < 4; k4++)
                mma_f16_ss(tb, adh + 2 * k4, bdh + 2 * k4, IDESC, (ks | k4) != 0);
#pragma unroll
            for (int k4 = 0; k4 < 4; k4++)
                mma_f16_ss(tb, adh + 2 * k4, bdl + 2 * k4, IDESC, 1);
#pragma unroll
            for (int k4 = 0; k4 < 4; k4++)
                mma_f16_ss(tb, adl + 2 * k4, bdh + 2 * k4, IDESC, 1);
            tc_commit(sb + MB_MMA + 8 * buf);
        }
    }

    mbar_wait(sb + MB_MMA + 8 * 3, 0);   // buf3 9th completion -> parity 0
    asm volatile("tcgen05.fence::after_thread_sync;" ::: "memory");

    if (tid < 128) {
        int m = bm0 + wid * 32 + lid;
        uint32_t r[32];
        LDTM_X32(r, tb);
        asm volatile("tcgen05.wait::ld.sync.aligned;" ::: "memory");
        if (finalOut) {
            int b = m >> 12, hw = m & 4095;
#pragma unroll
            for (int j = 0; j < 18; j++)
                finalOut[((size_t)(b * 18 + j)) * HW_ + hw] = __uint_as_float(r[j]);
        } else {
#pragma unroll
            for (int k = 0; k < 9; k++)
                make_record(m, k, __uint_as_float(r[2 * k]), __uint_as_float(r[2 * k + 1]));
        }
    }
    __syncthreads();
    if (wid == 0)
        asm volatile("tcgen05.dealloc.cta_group::1.sync.aligned.b32 %0, %1;"
                     :: "r"(tb), "r"(128u));
#endif
}

// ================= deform conv (N=256), 2-deep ring, bulk B ================
__global__ __launch_bounds__(256, 1)
void defconv_kernel(int fsel, int wsel)
{
#if HAS_TC
    constexpr int NB = 256 * 128;   // 32 KB per split
    constexpr uint32_t IDESC =
        (1u << 4) | (1u << 7) | (1u << 10) | (32u << 17) | (8u << 24);

    extern __shared__ char smem[];
    const uint32_t sb = smem_u32(smem);
    const int TMEMP = 0, MB_MMA = 16, MB_B = 32;
    const int SIDX = 64;            // 2 regions x 2048
    const int SWT  = 64 + 4096;     // 2 regions x 2048
    const int ABASE = 16384;        // 2 stages x 2 splits x 16KB = 64KB
    const int BBASE = 16384 + 65536;// 2 stages x 2 splits x 32KB = 128KB -> ends 212992

    const float* __restrict__ fin = fsel ? g_feat1 : g_feat0;
    float* __restrict__ fout      = fsel ? g_feat0 : g_feat1;
    const __nv_bfloat16* __restrict__ wsrc = g_wDs + (size_t)wsel * 9 * 4 * 2 * 16384;

    const int tid = threadIdx.x, wid = tid >> 5, lid = tid & 31;
    const int bm0 = blockIdx.x * 128;

    if (wid == 0) {
        asm volatile("tcgen05.alloc.cta_group::1.sync.aligned.shared::cta.b32 [%0], %1;"
                     :: "r"(sb + TMEMP), "r"(512u) : "memory");
        asm volatile("tcgen05.relinquish_alloc_permit.cta_group::1.sync.aligned;");
    }
    if (tid < 2) { mbar_init(sb + MB_MMA + 8 * tid, 1); mbar_init(sb + MB_B + 8 * tid, 1); }
    // stage tap 0 records into region 0
    if (tid < 128) {
        int m = bm0 + tid;
        ((int4*)(smem + SIDX))[tid]  = g_recIdx[(size_t)m * 9];
        ((float4*)(smem + SWT))[tid] = g_recW[(size_t)m * 9];
    }
    __syncthreads();
    uint32_t tb;
    asm volatile("ld.shared.b32 %0, [%1];" : "=r"(tb) : "r"(sb + TMEMP));

    const int cl4 = (lid & 15) * 4;
    const int ph  = (lid >> 4);

    for (int ks = 0; ks < 36; ++ks) {
        const int tap = ks >> 2, ch = ks & 3;
        const int buf = ks & 1;
        const int u = ks >> 1;
        if (u > 0) mbar_wait(sb + MB_MMA + 8 * buf, (u - 1) & 1);

        if (tid == 0) {
            mbar_expect_tx(sb + MB_B + 8 * buf, 2 * NB);
            bulk_g2s(sb + BBASE + (buf * 2 + 0) * NB,
                     (const char*)wsrc + (size_t)(ks * 2) * 32768, NB, sb + MB_B + 8 * buf);
            bulk_g2s(sb + BBASE + (buf * 2 + 1) * NB,
                     (const char*)wsrc + (size_t)(ks * 2) * 32768 + NB, NB, sb + MB_B + 8 * buf);
        }
        // prefetch next tap's records during first chunk of current tap
        if (ch == 0 && tap + 1 < 9 && tid < 128) {
            int m = bm0 + tid;
            int r = (tap + 1) & 1;
            ((int4*)(smem + SIDX + r * 2048))[tid]  = g_recIdx[(size_t)m * 9 + tap + 1];
            ((float4*)(smem + SWT + r * 2048))[tid] = g_recW[(size_t)m * 9 + tap + 1];
        }
        // A tile: gather + blend + split, 2 pixels per group with loads hoisted
        {
            char* ah = smem + ABASE + (buf * 2 + 0) * 16384;
            char* al = smem + ABASE + (buf * 2 + 1) * 16384;
            const int co = ch * 64 + cl4;
            const int4*   sI = (const int4*)(smem + SIDX + (tap & 1) * 2048);
            const float4* sW = (const float4*)(smem + SWT + (tap & 1) * 2048);
#pragma unroll
            for (int g = 0; g < 4; ++g) {
                int p0 = (2 * g) * 16 + wid * 2 + ph, p1 = p0 + 16;
                int4   i0 = sI[p0], i1 = sI[p1];
                float4 w0 = sW[p0], w1 = sW[p1];
                float4 a0 = __ldg((const float4*)(fin + i0.x + co));
                float4 b0 = __ldg((const float4*)(fin + i0.y + co));
                float4 c0 = __ldg((const float4*)(fin + i0.z + co));
                float4 d0 = __ldg((const float4*)(fin + i0.w + co));
                float4 a1 = __ldg((const float4*)(fin + i1.x + co));
                float4 b1 = __ldg((const float4*)(fin + i1.y + co));
                float4 c1 = __ldg((const float4*)(fin + i1.z + co));
                float4 d1 = __ldg((const float4*)(fin + i1.w + co));
                float4 r0, r1;
                r0.x = w0.x*a0.x + w0.y*b0.x + w0.z*c0.x + w0.w*d0.x;
                r0.y = w0.x*a0.y + w0.y*b0.y + w0.z*c0.y + w0.w*d0.y;
                r0.z = w0.x*a0.z + w0.y*b0.z + w0.z*c0.z + w0.w*d0.z;
                r0.w = w0.x*a0.w + w0.y*b0.w + w0.z*c0.w + w0.w*d0.w;
                r1.x = w1.x*a1.x + w1.y*b1.x + w1.z*c1.x + w1.w*d1.x;
                r1.y = w1.x*a1.y + w1.y*b1.y + w1.z*c1.y + w1.w*d1.y;
                r1.z = w1.x*a1.z + w1.y*b1.z + w1.z*c1.z + w1.w*d1.z;
                r1.w = w1.x*a1.w + w1.y*b1.w + w1.z*c1.w + w1.w*d1.w;
                uint2 hp0, lp0, hp1, lp1;
                split2(r0.x, r0.y, hp0.x, lp0.x);
                split2(r0.z, r0.w, hp0.y, lp0.y);
                split2(r1.x, r1.y, hp1.x, lp1.x);
                split2(r1.z, r1.w, hp1.y, lp1.y);
                uint32_t o0 = (uint32_t)(p0 * 128 + (lid & 15) * 8);
                uint32_t o1 = (uint32_t)(p1 * 128 + (lid & 15) * 8);
                uint32_t s0 = o0 ^ ((o0 >> 3) & 0x70);
                uint32_t s1 = o1 ^ ((o1 >> 3) & 0x70);
                *(uint2*)(ah + s0) = hp0; *(uint2*)(al + s0) = lp0;
                *(uint2*)(ah + s1) = hp1; *(uint2*)(al + s1) = lp1;
            }
        }
        asm volatile("fence.proxy.async.shared::cta;" ::: "memory");
        __syncthreads();

        if (tid == 0) {
            mbar_wait(sb + MB_B + 8 * buf, u & 1);
            asm volatile("tcgen05.fence::after_thread_sync;" ::: "memory");
            const uint64_t DB = (2ull << 61) | (1ull << 46) | (64ull << 32) | (1ull << 16);
            uint64_t adh = DB | (((sb + ABASE + (buf * 2 + 0) * 16384) >> 4) & 0x3FFF);
            uint64_t adl = DB | (((sb + ABASE + (buf * 2 + 1) * 16384) >> 4) & 0x3FFF);
            uint64_t bdh = DB | (((sb + BBASE + (buf * 2 + 0) * NB) >> 4) & 0x3FFF);
            uint64_t bdl = DB | (((sb + BBASE + (buf * 2 + 1) * NB) >> 4) & 0x3FFF);
#pragma unroll
            for (int k4 = 0; k4 < 4; k4++)
                mma_f16_ss(tb, adh + 2 * k4, bdh + 2 * k4, IDESC, (ks | k4) != 0);
#pragma unroll
            for (int k4 = 0; k4 < 4; k4++)
                mma_f16_ss(tb, adh + 2 * k4, bdl + 2 * k4, IDESC, 1);
#pragma unroll
            for (int k4 = 0; k4 < 4; k4++)
                mma_f16_ss(tb, adl + 2 * k4, bdh + 2 * k4, IDESC, 1);
            tc_commit(sb + MB_MMA + 8 * buf);
        }
    }

    mbar_wait(sb + MB_MMA + 8, 1);   // buf1 18th completion -> parity 1
    asm volatile("tcgen05.fence::after_thread_sync;" ::: "memory");

    if (tid < 128) {
        int m = bm0 + wid * 32 + lid;
#pragma unroll
        for (int nb = 0; nb < 8; nb++) {
            uint32_t r[32];
            LDTM_X32(r, tb + nb * 32);
            asm volatile("tcgen05.wait::ld.sync.aligned;" ::: "memory");
            float4* dst = (float4*)(fout + (size_t)m * 256 + nb * 32);
#pragma unroll
            for (int q = 0; q < 8; q++)
                dst[q] = make_float4(__uint_as_float(r[q*4+0]), __uint_as_float(r[q*4+1]),
                                     __uint_as_float(r[q*4+2]), __uint_as_float(r[q*4+3]));
        }
    }
    __syncthreads();
    if (wid == 0)
        asm volatile("tcgen05.dealloc.cta_group::1.sync.aligned.b32 %0, %1;"
                     :: "r"(tb), "r"(512u));
#endif
}

// ---------------------------------------------------------------------------
extern "C" void kernel_launch(void* const* d_in, const int* in_sizes, int n_in,
                              void* d_out, int out_size)
{
    (void)in_sizes; (void)n_in; (void)out_size;
    const float* x  = (const float*)d_in[0];
    const float* y  = (const float*)d_in[1];
    const float* oW = (const float*)d_in[2];
    const float* dW = (const float*)d_in[3];
    float* out = (float*)d_out;

    const int SMEM_D = 16384 + 65536 + 131072;   // 212992
    const int SMEM_O = 16384 + 131072 + 32768;   // 180224
    cudaFuncSetAttribute(defconv_kernel, cudaFuncAttributeMaxDynamicSharedMemorySize, SMEM_D);
    cudaFuncSetAttribute(offconv_kernel, cudaFuncAttributeMaxDynamicSharedMemorySize, SMEM_O);

    dim3 pb(32, 8), pg(HW_ / 32, C_ / 32, B_);
    pack_kernel<<<pg, pb>>>(x, y);

    const int G = 3 * 9 * 4 * 2048 + 4 * 9 * 4 * 256;
    wsplit_kernel<<<(G + 255) / 256, 256>>>(oW, dW);

    int fsel = 0;
    for (int it = 0; it < 3; ++it) {
        offconv_kernel<<<128, 256, SMEM_O>>>(fsel, it, nullptr);
        defconv_kernel<<<128, 256, SMEM_D>>>(fsel, it);
        fsel ^= 1;
    }
    offconv_kernel<<<128, 256, SMEM_O>>>(fsel, 3, out);
}

// round 16
// speedup vs baseline: 1.7893x; 1.2457x over previous
#include <cuda_runtime.h>
#include <cuda_bf16.h>
#include <cstdint>

#if defined(__CUDA_ARCH__) && (defined(__CUDA_ARCH_FEAT_SM103_ALL) || defined(__CUDA_ARCH_SPECIFIC__) || defined(__CUDA_ARCH_FAMILY_SPECIFIC__))
#define HAS_TC 1
#else
#define HAS_TC 0
#endif

static constexpr int B_  = 4;
static constexpr int H_  = 64;
static constexpr int W_  = 64;
static constexpr int C_  = 256;
static constexpr int HW_ = H_ * W_;   // 4096
static constexpr int M_  = B_ * HW_;  // 16384

// ---------------- device scratch -------------------------------------------
__device__ float  g_feat0[(size_t)M_ * C_];
__device__ float  g_feat1[(size_t)M_ * C_];
__device__ int4   g_recIdx[(size_t)M_ * 9];
__device__ float4 g_recW[(size_t)M_ * 9];
__device__ __nv_bfloat16 g_wDs[(size_t)3 * 9 * 4 * 2 * 256 * 64];
__device__ __nv_bfloat16 g_wOs[(size_t)4 * 9 * 4 * 2 * 32 * 64];

// ---------------- PTX helpers ----------------------------------------------
__device__ __forceinline__ uint32_t smem_u32(const void* p) {
    uint32_t a;
    asm("{ .reg .u64 t; cvta.to.shared.u64 t, %1; cvt.u32.u64 %0, t; }" : "=r"(a) : "l"(p));
    return a;
}
#if HAS_TC
__device__ __forceinline__ void mbar_init(uint32_t a, uint32_t cnt) {
    asm volatile("mbarrier.init.shared.b64 [%0], %1;" :: "r"(a), "r"(cnt) : "memory");
}
__device__ __forceinline__ void mbar_wait(uint32_t a, uint32_t phase) {
    asm volatile(
        "{\n\t.reg .pred P;\n\t"
        "WL_%=:\n\t"
        "mbarrier.try_wait.parity.acquire.cta.shared::cta.b64 P, [%0], %1, 0x989680;\n\t"
        "@P bra.uni WD_%=;\n\t"
        "bra.uni WL_%=;\n\t"
        "WD_%=:\n\t}"
        :: "r"(a), "r"(phase) : "memory");
}
__device__ __forceinline__ void mbar_expect_tx(uint32_t a, uint32_t bytes) {
    asm volatile("mbarrier.arrive.expect_tx.shared.b64 _, [%0], %1;"
                 :: "r"(a), "r"(bytes) : "memory");
}
__device__ __forceinline__ void bulk_g2s(uint32_t dst, const void* src,
                                         uint32_t bytes, uint32_t mbar) {
    asm volatile(
        "cp.async.bulk.shared::cta.global.mbarrier::complete_tx::bytes [%0], [%1], %2, [%3];"
        :: "r"(dst), "l"(src), "r"(bytes), "r"(mbar) : "memory");
}
__device__ __forceinline__ void tc_commit(uint32_t mbar) {
    asm volatile(
        "tcgen05.commit.cta_group::1.mbarrier::arrive::one.shared::cluster.b64 [%0];"
        :: "r"(mbar) : "memory");
}
__device__ __forceinline__ void mma_f16_ss(uint32_t d, uint64_t ad, uint64_t bd,
                                           uint32_t idesc, uint32_t en) {
    asm volatile(
        "{\n\t.reg .pred p;\n\t"
        "setp.ne.u32 p, %4, 0;\n\t"
        "tcgen05.mma.cta_group::1.kind::f16 [%0], %1, %2, %3, {%5,%5,%5,%5}, p;\n\t}"
        :: "r"(d), "l"(ad), "l"(bd), "r"(idesc), "r"(en), "r"(0u) : "memory");
}
__device__ __forceinline__ void split2(float a, float b, uint32_t& hp, uint32_t& lp) {
    asm("cvt.rn.bf16x2.f32 %0, %1, %2;" : "=r"(hp) : "f"(b), "f"(a));
    float fa = __uint_as_float(hp << 16);
    float fb = __uint_as_float(hp & 0xFFFF0000u);
    float la = a - fa, lb = b - fb;
    asm("cvt.rn.bf16x2.f32 %0, %1, %2;" : "=r"(lp) : "f"(lb), "f"(la));
}
#define LDTM_X32(r, addr) \
    asm volatile( \
        "tcgen05.ld.sync.aligned.32x32b.x32.b32 " \
        "{%0,%1,%2,%3,%4,%5,%6,%7,%8,%9,%10,%11,%12,%13,%14,%15," \
        "%16,%17,%18,%19,%20,%21,%22,%23,%24,%25,%26,%27,%28,%29,%30,%31}, [%32];" \
        : "=r"((r)[0]),"=r"((r)[1]),"=r"((r)[2]),"=r"((r)[3]), \
          "=r"((r)[4]),"=r"((r)[5]),"=r"((r)[6]),"=r"((r)[7]), \
          "=r"((r)[8]),"=r"((r)[9]),"=r"((r)[10]),"=r"((r)[11]), \
          "=r"((r)[12]),"=r"((r)[13]),"=r"((r)[14]),"=r"((r)[15]), \
          "=r"((r)[16]),"=r"((r)[17]),"=r"((r)[18]),"=r"((r)[19]), \
          "=r"((r)[20]),"=r"((r)[21]),"=r"((r)[22]),"=r"((r)[23]), \
          "=r"((r)[24]),"=r"((r)[25]),"=r"((r)[26]),"=r"((r)[27]), \
          "=r"((r)[28]),"=r"((r)[29]),"=r"((r)[30]),"=r"((r)[31]) \
        : "r"(addr))
#endif

// ---------------- pack: NCHW x,y -> NHWC concat feat0 ----------------------
__global__ void pack_kernel(const float* __restrict__ x, const float* __restrict__ y)
{
    __shared__ float t[32][33];
    int b = blockIdx.z, hw0 = blockIdx.x * 32, c0 = blockIdx.y * 32;
    int tx = threadIdx.x, ty = threadIdx.y;
#pragma unroll
    for (int i = 0; i < 32; i += 8) {
        int c = c0 + ty + i;
        const float* s = (c < 128) ? (x + ((size_t)b * 128 + c) * HW_)
                                   : (y + ((size_t)b * 128 + (c - 128)) * HW_);
        t[ty + i][tx] = s[hw0 + tx];
    }
    __syncthreads();
#pragma unroll
    for (int i = 0; i < 32; i += 8)
        g_feat0[((size_t)b * HW_ + hw0 + ty + i) * C_ + c0 + tx] = t[tx][ty + i];
}

// ---------------- weight split + pre-swizzle --------------------------------
__global__ void wsplit_kernel(const float* __restrict__ oW, const float* __restrict__ dW)
{
#if HAS_TC
    const int GD = 3 * 9 * 4 * 2048;
    const int GO = 4 * 9 * 4 * 256;
    int g = blockIdx.x * blockDim.x + threadIdx.x;
    if (g >= GD + GO) return;
    if (g < GD) {
        int t = g >> 11, o = g & 2047;
        int chunk = t & 3, tap = (t >> 2) % 9, it = (t >> 2) / 9;
        uint32_t boff = (uint32_t)o * 16;
        uint32_t un = boff ^ ((boff >> 3) & 0x70);
        int n = un >> 7, k0 = (un & 127) >> 1;
        uint32_t hp[4], lp[4];
#pragma unroll
        for (int j2 = 0; j2 < 4; j2++) {
            float v0 = dW[((size_t)(it * 256 + n) * 256 + (size_t)(chunk * 64 + k0 + j2 * 2)) * 9 + tap];
            float v1 = dW[((size_t)(it * 256 + n) * 256 + (size_t)(chunk * 64 + k0 + j2 * 2 + 1)) * 9 + tap];
            split2(v0, v1, hp[j2], lp[j2]);
        }
        char* base = (char*)(g_wDs + (size_t)(((it * 9 + tap) * 4 + chunk) * 2) * 16384);
        *(uint4*)(base + boff)         = make_uint4(hp[0], hp[1], hp[2], hp[3]);
        *(uint4*)(base + 32768 + boff) = make_uint4(lp[0], lp[1], lp[2], lp[3]);
    } else {
        int g2 = g - GD;
        int t = g2 >> 8, o = g2 & 255;
        int chunk = t & 3, tap = (t >> 2) % 9, it = (t >> 2) / 9;
        uint32_t boff = (uint32_t)o * 16;
        uint32_t un = boff ^ ((boff >> 3) & 0x70);
        int n = un >> 7, k0 = (un & 127) >> 1;
        uint32_t hp[4], lp[4];
#pragma unroll
        for (int j2 = 0; j2 < 4; j2++) {
            float v0 = (n < 18) ? oW[((size_t)(it * 18 + n) * 256 + (size_t)(chunk * 64 + k0 + j2 * 2)) * 9 + tap] : 0.f;
            float v1 = (n < 18) ? oW[((size_t)(it * 18 + n) * 256 + (size_t)(chunk * 64 + k0 + j2 * 2 + 1)) * 9 + tap] : 0.f;
            split2(v0, v1, hp[j2], lp[j2]);
        }
        char* base = (char*)(g_wOs + (size_t)(((it * 9 + tap) * 4 + chunk) * 2) * 2048);
        *(uint4*)(base + boff)        = make_uint4(hp[0], hp[1], hp[2], hp[3]);
        *(uint4*)(base + 4096 + boff) = make_uint4(lp[0], lp[1], lp[2], lp[3]);
    }
#endif
}

#if HAS_TC
__device__ __forceinline__ void make_record(int m, int k, float dy, float dx)
{
    int b = m >> 12, hw = m & 4095, h = hw >> 6, w = hw & 63;
    float py = dy + (float)(k / 3 - 1) + (float)h;
    float px = dx + (float)(k % 3 - 1) + (float)w;
    float y0f = floorf(py), x0f = floorf(px);
    float wy1 = py - y0f, wy0 = 1.f - wy1;
    float wx1 = px - x0f, wx0 = 1.f - wx1;
    int y0 = (int)y0f, x0 = (int)x0f, y1 = y0 + 1, x1 = x0 + 1;
    int4 ii; float4 ww;
    {
        bool v = (y0 >= 0 && y0 < H_ && x0 >= 0 && x0 < W_);
        int yc = min(max(y0,0),H_-1), xc = min(max(x0,0),W_-1);
        ii.x = ((b << 12) + (yc << 6) + xc) << 8;  ww.x = v ? wy0 * wx0 : 0.f;
    }
    {
        bool v = (y0 >= 0 && y0 < H_ && x1 >= 0 && x1 < W_);
        int yc = min(max(y0,0),H_-1), xc = min(max(x1,0),W_-1);
        ii.y = ((b << 12) + (yc << 6) + xc) << 8;  ww.y = v ? wy0 * wx1 : 0.f;
    }
    {
        bool v = (y1 >= 0 && y1 < H_ && x0 >= 0 && x0 < W_);
        int yc = min(max(y1,0),H_-1), xc = min(max(x0,0),W_-1);
        ii.z = ((b << 12) + (yc << 6) + xc) << 8;  ww.z = v ? wy1 * wx0 : 0.f;
    }
    {
        bool v = (y1 >= 0 && y1 < H_ && x1 >= 0 && x1 < W_);
        int yc = min(max(y1,0),H_-1), xc = min(max(x1,0),W_-1);
        ii.w = ((b << 12) + (yc << 6) + xc) << 8;  ww.w = v ? wy1 * wx1 : 0.f;
    }
    g_recIdx[(size_t)m * 9 + k] = ii;
    g_recW[(size_t)m * 9 + k]   = ww;
}
#endif

// ================= offset conv (N=32), 4-deep ring, 512 thr ================
__global__ __launch_bounds__(512, 1)
void offconv_kernel(int fsel, int wsel, float* __restrict__ finalOut)
{
#if HAS_TC
    constexpr int NB = 32 * 128;   // 4 KB per split
    constexpr uint32_t IDESC =
        (1u << 4) | (1u << 7) | (1u << 10) | (4u << 17) | (8u << 24);

    extern __shared__ char smem[];
    const uint32_t sb = smem_u32(smem);
    const int TMEMP = 0, MB_MMA = 16, MB_B = 48, SIDX = 128;
    const int ABASE = 16384;                  // 4 stages x 2 splits x 16KB = 128KB
    const int BBASE = 16384 + 131072;         // 4 stages x 2 splits x 4KB  = 32KB

    const float* __restrict__ fin = fsel ? g_feat1 : g_feat0;
    const __nv_bfloat16* __restrict__ wsrc = g_wOs + (size_t)wsel * 9 * 4 * 2 * 2048;

    const int tid = threadIdx.x, wid = tid >> 5, lid = tid & 31;
    const int bm0 = blockIdx.x * 128;

    if (wid == 0) {
        asm volatile("tcgen05.alloc.cta_group::1.sync.aligned.shared::cta.b32 [%0], %1;"
                     :: "r"(sb + TMEMP), "r"(128u) : "memory");
        asm volatile("tcgen05.relinquish_alloc_permit.cta_group::1.sync.aligned;");
    }
    if (tid < 4) { mbar_init(sb + MB_MMA + 8 * tid, 1); mbar_init(sb + MB_B + 8 * tid, 1); }
    for (int t = tid; t < 9 * 128; t += 512) {
        int tap = t >> 7, p = t & 127;
        int m = bm0 + p;
        int b = m >> 12, hw = m & 4095, h = hw >> 6, w = hw & 63;
        int yy = h + tap / 3 - 1, xx = w + tap % 3 - 1;
        ((int*)(smem + SIDX))[t] =
            (yy >= 0 && yy < H_ && xx >= 0 && xx < W_)
                ? (((b << 12) + (yy << 6) + xx) << 8) : -1;
    }
    __syncthreads();
    uint32_t tb;
    asm volatile("ld.shared.b32 %0, [%1];" : "=r"(tb) : "r"(sb + TMEMP));

    const int grp = tid >> 4;          // 0..31
    const int cl4 = (tid & 15) * 4;    // channel-in-chunk
    const int bso = (tid & 15) * 8;    // byte offset within row

    for (int ks = 0; ks < 36; ++ks) {
        const int tap = ks >> 2, ch = ks & 3;
        const int buf = ks & 3;
        const int u = ks >> 2;
        if (u > 0) mbar_wait(sb + MB_MMA + 8 * buf, (u - 1) & 1);

        if (tid == 0) {
            mbar_expect_tx(sb + MB_B + 8 * buf, 2 * NB);
            bulk_g2s(sb + BBASE + (buf * 2 + 0) * NB,
                     (const char*)wsrc + (size_t)(ks * 2) * 4096, NB, sb + MB_B + 8 * buf);
            bulk_g2s(sb + BBASE + (buf * 2 + 1) * NB,
                     (const char*)wsrc + (size_t)(ks * 2) * 4096 + NB, NB, sb + MB_B + 8 * buf);
        }
        {
            char* ah = smem + ABASE + (buf * 2 + 0) * 16384;
            char* al = smem + ABASE + (buf * 2 + 1) * 16384;
            const int co = ch * 64 + cl4;
            const int* sidx = (const int*)(smem + SIDX) + tap * 128;
#pragma unroll
            for (int g = 0; g < 2; ++g) {
                int p0 = g * 32 + grp, p1 = p0 + 64;
                int b0 = sidx[p0], b1 = sidx[p1];
                float4 r0 = make_float4(0.f,0.f,0.f,0.f), r1 = r0;
                if (b0 >= 0) r0 = __ldg((const float4*)(fin + b0 + co));
                if (b1 >= 0) r1 = __ldg((const float4*)(fin + b1 + co));
                uint2 hp0, lp0, hp1, lp1;
                split2(r0.x, r0.y, hp0.x, lp0.x);
                split2(r0.z, r0.w, hp0.y, lp0.y);
                split2(r1.x, r1.y, hp1.x, lp1.x);
                split2(r1.z, r1.w, hp1.y, lp1.y);
                uint32_t o0 = (uint32_t)(p0 * 128 + bso);
                uint32_t o1 = (uint32_t)(p1 * 128 + bso);
                uint32_t s0 = o0 ^ ((o0 >> 3) & 0x70);
                uint32_t s1 = o1 ^ ((o1 >> 3) & 0x70);
                *(uint2*)(ah + s0) = hp0; *(uint2*)(al + s0) = lp0;
                *(uint2*)(ah + s1) = hp1; *(uint2*)(al + s1) = lp1;
            }
        }
        asm volatile("fence.proxy.async.shared::cta;" ::: "memory");
        __syncthreads();

        if (tid == 0) {
            mbar_wait(sb + MB_B + 8 * buf, u & 1);
            asm volatile("tcgen05.fence::after_thread_sync;" ::: "memory");
            const uint64_t DB = (2ull << 61) | (1ull << 46) | (64ull << 32) | (1ull << 16);
            uint64_t adh = DB | (((sb + ABASE + (buf * 2 + 0) * 16384) >> 4) & 0x3FFF);
            uint64_t adl = DB | (((sb + ABASE + (buf * 2 + 1) * 16384) >> 4) & 0x3FFF);
            uint64_t bdh = DB | (((sb + BBASE + (buf * 2 + 0) * NB) >> 4) & 0x3FFF);
            uint64_t bdl = DB | (((sb + BBASE + (buf * 2 + 1) * NB) >> 4) & 0x3FFF);
#pragma unroll
            for (int k4 = 0; k4 < 4; k4++)
                mma_f16_ss(tb, adh + 2 * k4, bdh + 2 * k4, IDESC, (ks | k4) != 0);
#pragma unroll
            for (int k4 = 0; k4 < 4; k4++)
                mma_f16_ss(tb, adh + 2 * k4, bdl + 2 * k4, IDESC, 1);
#pragma unroll
            for (int k4 = 0; k4 < 4; k4++)
                mma_f16_ss(tb, adl + 2 * k4, bdh + 2 * k4, IDESC, 1);
            tc_commit(sb + MB_MMA + 8 * buf);
        }
    }

    mbar_wait(sb + MB_MMA + 8 * 3, 0);   // buf3 9th completion -> parity 0
    asm volatile("tcgen05.fence::after_thread_sync;" ::: "memory");

    if (tid < 128) {
        int m = bm0 + wid * 32 + lid;
        uint32_t r[32];
        LDTM_X32(r, tb);
        asm volatile("tcgen05.wait::ld.sync.aligned;" ::: "memory");
        if (finalOut) {
            int b = m >> 12, hw = m & 4095;
#pragma unroll
            for (int j = 0; j < 18; j++)
                finalOut[((size_t)(b * 18 + j)) * HW_ + hw] = __uint_as_float(r[j]);
        } else {
#pragma unroll
            for (int k = 0; k < 9; k++)
                make_record(m, k, __uint_as_float(r[2 * k]), __uint_as_float(r[2 * k + 1]));
        }
    }
    __syncthreads();
    if (wid == 0)
        asm volatile("tcgen05.dealloc.cta_group::1.sync.aligned.b32 %0, %1;"
                     :: "r"(tb), "r"(128u));
#endif
}

// ================= deform conv (N=256), 2-deep ring, 512 thr ===============
__global__ __launch_bounds__(512, 1)
void defconv_kernel(int fsel, int wsel)
{
#if HAS_TC
    constexpr int NB = 256 * 128;   // 32 KB per split
    constexpr uint32_t IDESC =
        (1u << 4) | (1u << 7) | (1u << 10) | (32u << 17) | (8u << 24);

    extern __shared__ char smem[];
    const uint32_t sb = smem_u32(smem);
    const int TMEMP = 0, MB_MMA = 16, MB_B = 32;
    const int SIDX = 64;            // 2 regions x 2048
    const int SWT  = 64 + 4096;     // 2 regions x 2048
    const int ABASE = 16384;        // 2 stages x 2 splits x 16KB = 64KB
    const int BBASE = 16384 + 65536;// 2 stages x 2 splits x 32KB = 128KB

    const float* __restrict__ fin = fsel ? g_feat1 : g_feat0;
    float* __restrict__ fout      = fsel ? g_feat0 : g_feat1;
    const __nv_bfloat16* __restrict__ wsrc = g_wDs + (size_t)wsel * 9 * 4 * 2 * 16384;

    const int tid = threadIdx.x, wid = tid >> 5, lid = tid & 31;
    const int bm0 = blockIdx.x * 128;

    if (wid == 0) {
        asm volatile("tcgen05.alloc.cta_group::1.sync.aligned.shared::cta.b32 [%0], %1;"
                     :: "r"(sb + TMEMP), "r"(512u) : "memory");
        asm volatile("tcgen05.relinquish_alloc_permit.cta_group::1.sync.aligned;");
    }
    if (tid < 2) { mbar_init(sb + MB_MMA + 8 * tid, 1); mbar_init(sb + MB_B + 8 * tid, 1); }
    if (tid < 128) {
        int m = bm0 + tid;
        ((int4*)(smem + SIDX))[tid]  = g_recIdx[(size_t)m * 9];
        ((float4*)(smem + SWT))[tid] = g_recW[(size_t)m * 9];
    }
    __syncthreads();
    uint32_t tb;
    asm volatile("ld.shared.b32 %0, [%1];" : "=r"(tb) : "r"(sb + TMEMP));

    const int grp = tid >> 4;          // 0..31
    const int cl4 = (tid & 15) * 4;
    const int bso = (tid & 15) * 8;

    for (int ks = 0; ks < 36; ++ks) {
        const int tap = ks >> 2, ch = ks & 3;
        const int buf = ks & 1;
        const int u = ks >> 1;
        if (u > 0) mbar_wait(sb + MB_MMA + 8 * buf, (u - 1) & 1);

        if (tid == 0) {
            mbar_expect_tx(sb + MB_B + 8 * buf, 2 * NB);
            bulk_g2s(sb + BBASE + (buf * 2 + 0) * NB,
                     (const char*)wsrc + (size_t)(ks * 2) * 32768, NB, sb + MB_B + 8 * buf);
            bulk_g2s(sb + BBASE + (buf * 2 + 1) * NB,
                     (const char*)wsrc + (size_t)(ks * 2) * 32768 + NB, NB, sb + MB_B + 8 * buf);
        }
        if (ch == 0 && tap + 1 < 9 && tid < 128) {
            int m = bm0 + tid;
            int r = (tap + 1) & 1;
            ((int4*)(smem + SIDX + r * 2048))[tid]  = g_recIdx[(size_t)m * 9 + tap + 1];
            ((float4*)(smem + SWT + r * 2048))[tid] = g_recW[(size_t)m * 9 + tap + 1];
        }
        {
            char* ah = smem + ABASE + (buf * 2 + 0) * 16384;
            char* al = smem + ABASE + (buf * 2 + 1) * 16384;
            const int co = ch * 64 + cl4;
            const int4*   sI = (const int4*)(smem + SIDX + (tap & 1) * 2048);
            const float4* sW = (const float4*)(smem + SWT + (tap & 1) * 2048);
#pragma unroll
            for (int g = 0; g < 2; ++g) {
                int p0 = g * 32 + grp, p1 = p0 + 64;
                int4   i0 = sI[p0], i1 = sI[p1];
                float4 w0 = sW[p0], w1 = sW[p1];
                float4 a0 = __ldg((const float4*)(fin + i0.x + co));
                float4 b0 = __ldg((const float4*)(fin + i0.y + co));
                float4 c0 = __ldg((const float4*)(fin + i0.z + co));
                float4 d0 = __ldg((const float4*)(fin + i0.w + co));
                float4 a1 = __ldg((const float4*)(fin + i1.x + co));
                float4 b1 = __ldg((const float4*)(fin + i1.y + co));
                float4 c1 = __ldg((const float4*)(fin + i1.z + co));
                float4 d1 = __ldg((const float4*)(fin + i1.w + co));
                float4 r0, r1;
                r0.x = w0.x*a0.x + w0.y*b0.x + w0.z*c0.x + w0.w*d0.x;
                r0.y = w0.x*a0.y + w0.y*b0.y + w0.z*c0.y + w0.w*d0.y;
                r0.z = w0.x*a0.z + w0.y*b0.z + w0.z*c0.z + w0.w*d0.z;
                r0.w = w0.x*a0.w + w0.y*b0.w + w0.z*c0.w + w0.w*d0.w;
                r1.x = w1.x*a1.x + w1.y*b1.x + w1.z*c1.x + w1.w*d1.x;
                r1.y = w1.x*a1.y + w1.y*b1.y + w1.z*c1.y + w1.w*d1.y;
                r1.z = w1.x*a1.z + w1.y*b1.z + w1.z*c1.z + w1.w*d1.z;
                r1.w = w1.x*a1.w + w1.y*b1.w + w1.z*c1.w + w1.w*d1.w;
                uint2 hp0, lp0, hp1, lp1;
                split2(r0.x, r0.y, hp0.x, lp0.x);
                split2(r0.z, r0.w, hp0.y, lp0.y);
                split2(r1.x, r1.y, hp1.x, lp1.x);
                split2(r1.z, r1.w, hp1.y, lp1.y);
                uint32_t o0 = (uint32_t)(p0 * 128 + bso);
                uint32_t o1 = (uint32_t)(p1 * 128 + bso);
                uint32_t s0 = o0 ^ ((o0 >> 3) & 0x70);
                uint32_t s1 = o1 ^ ((o1 >> 3) & 0x70);
                *(uint2*)(ah + s0) = hp0; *(uint2*)(al + s0) = lp0;
                *(uint2*)(ah + s1) = hp1; *(uint2*)(al + s1) = lp1;
            }
        }
        asm volatile("fence.proxy.async.shared::cta;" ::: "memory");
        __syncthreads();

        if (tid == 0) {
            mbar_wait(sb + MB_B + 8 * buf, u & 1);
            asm volatile("tcgen05.fence::after_thread_sync;" ::: "memory");
            const uint64_t DB = (2ull << 61) | (1ull << 46) | (64ull << 32) | (1ull << 16);
            uint64_t adh = DB | (((sb + ABASE + (buf * 2 + 0) * 16384) >> 4) & 0x3FFF);
            uint64_t adl = DB | (((sb + ABASE + (buf * 2 + 1) * 16384) >> 4) & 0x3FFF);
            uint64_t bdh = DB | (((sb + BBASE + (buf * 2 + 0) * NB) >> 4) & 0x3FFF);
            uint64_t bdl = DB | (((sb + BBASE + (buf * 2 + 1) * NB) >> 4) & 0x3FFF);
#pragma unroll
            for (int k4 = 0; k4 < 4; k4++)
                mma_f16_ss(tb, adh + 2 * k4, bdh + 2 * k4, IDESC, (ks | k4) != 0);
#pragma unroll
            for (int k4 = 0; k4 < 4; k4++)
                mma_f16_ss(tb, adh + 2 * k4, bdl + 2 * k4, IDESC, 1);
#pragma unroll
            for (int k4 = 0; k4 < 4; k4++)
                mma_f16_ss(tb, adl + 2 * k4, bdh + 2 * k4, IDESC, 1);
            tc_commit(sb + MB_MMA + 8 * buf);
        }
    }

    mbar_wait(sb + MB_MMA + 8, 1);   // buf1 18th completion -> parity 1
    asm volatile("tcgen05.fence::after_thread_sync;" ::: "memory");

    if (tid < 128) {
        int m = bm0 + wid * 32 + lid;
#pragma unroll
        for (int nb = 0; nb < 8; nb++) {
            uint32_t r[32];
            LDTM_X32(r, tb + nb * 32);
            asm volatile("tcgen05.wait::ld.sync.aligned;" ::: "memory");
            float4* dst = (float4*)(fout + (size_t)m * 256 + nb * 32);
#pragma unroll
            for (int q = 0; q < 8; q++)
                dst[q] = make_float4(__uint_as_float(r[q*4+0]), __uint_as_float(r[q*4+1]),
                                     __uint_as_float(r[q*4+2]), __uint_as_float(r[q*4+3]));
        }
    }
    __syncthreads();
    if (wid == 0)
        asm volatile("tcgen05.dealloc.cta_group::1.sync.aligned.b32 %0, %1;"
                     :: "r"(tb), "r"(512u));
#endif
}

// ---------------------------------------------------------------------------
extern "C" void kernel_launch(void* const* d_in, const int* in_sizes, int n_in,
                              void* d_out, int out_size)
{
    (void)in_sizes; (void)n_in; (void)out_size;
    const float* x  = (const float*)d_in[0];
    const float* y  = (const float*)d_in[1];
    const float* oW = (const float*)d_in[2];
    const float* dW = (const float*)d_in[3];
    float* out = (float*)d_out;

    const int SMEM_D = 16384 + 65536 + 131072;   // 212992
    const int SMEM_O = 16384 + 131072 + 32768;   // 180224
    cudaFuncSetAttribute(defconv_kernel, cudaFuncAttributeMaxDynamicSharedMemorySize, SMEM_D);
    cudaFuncSetAttribute(offconv_kernel, cudaFuncAttributeMaxDynamicSharedMemorySize, SMEM_O);

    dim3 pb(32, 8), pg(HW_ / 32, C_ / 32, B_);
    pack_kernel<<<pg, pb>>>(x, y);

    const int G = 3 * 9 * 4 * 2048 + 4 * 9 * 4 * 256;
    wsplit_kernel<<<(G + 255) / 256, 256>>>(oW, dW);

    int fsel = 0;
    for (int it = 0; it < 3; ++it) {
        offconv_kernel<<<128, 512, SMEM_O>>>(fsel, it, nullptr);
        defconv_kernel<<<128, 512, SMEM_D>>>(fsel, it);
        fsel ^= 1;
    }
    offconv_kernel<<<128, 512, SMEM_O>>>(fsel, 3, out);
}

// round 17
// speedup vs baseline: 2.0258x; 1.1322x over previous
#include <cuda_runtime.h>
#include <cuda_bf16.h>
#include <cstdint>

#if defined(__CUDA_ARCH__) && (defined(__CUDA_ARCH_FEAT_SM103_ALL) || defined(__CUDA_ARCH_SPECIFIC__) || defined(__CUDA_ARCH_FAMILY_SPECIFIC__))
#define HAS_TC 1
#else
#define HAS_TC 0
#endif

static constexpr int B_  = 4;
static constexpr int H_  = 64;
static constexpr int W_  = 64;
static constexpr int C_  = 256;
static constexpr int HW_ = H_ * W_;   // 4096
static constexpr int M_  = B_ * HW_;  // 16384

// ---------------- device scratch -------------------------------------------
__device__ float  g_feat0[(size_t)M_ * C_];
__device__ float  g_feat1[(size_t)M_ * C_];
__device__ int4   g_recIdx[(size_t)M_ * 9];
__device__ float4 g_recW[(size_t)M_ * 9];
__device__ __nv_bfloat16 g_wDs[(size_t)3 * 9 * 4 * 2 * 256 * 64];
__device__ __nv_bfloat16 g_wOs[(size_t)4 * 9 * 4 * 2 * 32 * 64];

// ---------------- PTX helpers ----------------------------------------------
__device__ __forceinline__ uint32_t smem_u32(const void* p) {
    uint32_t a;
    asm("{ .reg .u64 t; cvta.to.shared.u64 t, %1; cvt.u32.u64 %0, t; }" : "=r"(a) : "l"(p));
    return a;
}
#if HAS_TC
__device__ __forceinline__ void mbar_init(uint32_t a, uint32_t cnt) {
    asm volatile("mbarrier.init.shared.b64 [%0], %1;" :: "r"(a), "r"(cnt) : "memory");
}
__device__ __forceinline__ void mbar_wait(uint32_t a, uint32_t phase) {
    asm volatile(
        "{\n\t.reg .pred P;\n\t"
        "WL_%=:\n\t"
        "mbarrier.try_wait.parity.acquire.cta.shared::cta.b64 P, [%0], %1, 0x989680;\n\t"
        "@P bra.uni WD_%=;\n\t"
        "bra.uni WL_%=;\n\t"
        "WD_%=:\n\t}"
        :: "r"(a), "r"(phase) : "memory");
}
__device__ __forceinline__ void mbar_expect_tx(uint32_t a, uint32_t bytes) {
    asm volatile("mbarrier.arrive.expect_tx.shared.b64 _, [%0], %1;"
                 :: "r"(a), "r"(bytes) : "memory");
}
__device__ __forceinline__ void bulk_g2s(uint32_t dst, const void* src,
                                         uint32_t bytes, uint32_t mbar) {
    asm volatile(
        "cp.async.bulk.shared::cta.global.mbarrier::complete_tx::bytes [%0], [%1], %2, [%3];"
        :: "r"(dst), "l"(src), "r"(bytes), "r"(mbar) : "memory");
}
__device__ __forceinline__ void tc_commit(uint32_t mbar) {
    asm volatile(
        "tcgen05.commit.cta_group::1.mbarrier::arrive::one.shared::cluster.b64 [%0];"
        :: "r"(mbar) : "memory");
}
__device__ __forceinline__ void mma_f16_ss(uint32_t d, uint64_t ad, uint64_t bd,
                                           uint32_t idesc, uint32_t en) {
    asm volatile(
        "{\n\t.reg .pred p;\n\t"
        "setp.ne.u32 p, %4, 0;\n\t"
        "tcgen05.mma.cta_group::1.kind::f16 [%0], %1, %2, %3, {%5,%5,%5,%5}, p;\n\t}"
        :: "r"(d), "l"(ad), "l"(bd), "r"(idesc), "r"(en), "r"(0u) : "memory");
}
__device__ __forceinline__ void split2(float a, float b, uint32_t& hp, uint32_t& lp) {
    asm("cvt.rn.bf16x2.f32 %0, %1, %2;" : "=r"(hp) : "f"(b), "f"(a));
    float fa = __uint_as_float(hp << 16);
    float fb = __uint_as_float(hp & 0xFFFF0000u);
    float la = a - fa, lb = b - fb;
    asm("cvt.rn.bf16x2.f32 %0, %1, %2;" : "=r"(lp) : "f"(lb), "f"(la));
}
#define LDTM_X32(r, addr) \
    asm volatile( \
        "tcgen05.ld.sync.aligned.32x32b.x32.b32 " \
        "{%0,%1,%2,%3,%4,%5,%6,%7,%8,%9,%10,%11,%12,%13,%14,%15," \
        "%16,%17,%18,%19,%20,%21,%22,%23,%24,%25,%26,%27,%28,%29,%30,%31}, [%32];" \
        : "=r"((r)[0]),"=r"((r)[1]),"=r"((r)[2]),"=r"((r)[3]), \
          "=r"((r)[4]),"=r"((r)[5]),"=r"((r)[6]),"=r"((r)[7]), \
          "=r"((r)[8]),"=r"((r)[9]),"=r"((r)[10]),"=r"((r)[11]), \
          "=r"((r)[12]),"=r"((r)[13]),"=r"((r)[14]),"=r"((r)[15]), \
          "=r"((r)[16]),"=r"((r)[17]),"=r"((r)[18]),"=r"((r)[19]), \
          "=r"((r)[20]),"=r"((r)[21]),"=r"((r)[22]),"=r"((r)[23]), \
          "=r"((r)[24]),"=r"((r)[25]),"=r"((r)[26]),"=r"((r)[27]), \
          "=r"((r)[28]),"=r"((r)[29]),"=r"((r)[30]),"=r"((r)[31]) \
        : "r"(addr))
#endif

// ---------------- pack: NCHW x,y -> NHWC concat feat0 ----------------------
__global__ void pack_kernel(const float* __restrict__ x, const float* __restrict__ y)
{
    __shared__ float t[32][33];
    int b = blockIdx.z, hw0 = blockIdx.x * 32, c0 = blockIdx.y * 32;
    int tx = threadIdx.x, ty = threadIdx.y;
#pragma unroll
    for (int i = 0; i < 32; i += 8) {
        int c = c0 + ty + i;
        const float* s = (c < 128) ? (x + ((size_t)b * 128 + c) * HW_)
                                   : (y + ((size_t)b * 128 + (c - 128)) * HW_);
        t[ty + i][tx] = s[hw0 + tx];
    }
    __syncthreads();
#pragma unroll
    for (int i = 0; i < 32; i += 8)
        g_feat0[((size_t)b * HW_ + hw0 + ty + i) * C_ + c0 + tx] = t[tx][ty + i];
}

// ---------------- weight split + pre-swizzle --------------------------------
__global__ void wsplit_kernel(const float* __restrict__ oW, const float* __restrict__ dW)
{
#if HAS_TC
    const int GD = 3 * 9 * 4 * 2048;
    const int GO = 4 * 9 * 4 * 256;
    int g = blockIdx.x * blockDim.x + threadIdx.x;
    if (g >= GD + GO) return;
    if (g < GD) {
        int t = g >> 11, o = g & 2047;
        int chunk = t & 3, tap = (t >> 2) % 9, it = (t >> 2) / 9;
        uint32_t boff = (uint32_t)o * 16;
        uint32_t un = boff ^ ((boff >> 3) & 0x70);
        int n = un >> 7, k0 = (un & 127) >> 1;
        uint32_t hp[4], lp[4];
#pragma unroll
        for (int j2 = 0; j2 < 4; j2++) {
            float v0 = dW[((size_t)(it * 256 + n) * 256 + (size_t)(chunk * 64 + k0 + j2 * 2)) * 9 + tap];
            float v1 = dW[((size_t)(it * 256 + n) * 256 + (size_t)(chunk * 64 + k0 + j2 * 2 + 1)) * 9 + tap];
            split2(v0, v1, hp[j2], lp[j2]);
        }
        char* base = (char*)(g_wDs + (size_t)(((it * 9 + tap) * 4 + chunk) * 2) * 16384);
        *(uint4*)(base + boff)         = make_uint4(hp[0], hp[1], hp[2], hp[3]);
        *(uint4*)(base + 32768 + boff) = make_uint4(lp[0], lp[1], lp[2], lp[3]);
    } else {
        int g2 = g - GD;
        int t = g2 >> 8, o = g2 & 255;
        int chunk = t & 3, tap = (t >> 2) % 9, it = (t >> 2) / 9;
        uint32_t boff = (uint32_t)o * 16;
        uint32_t un = boff ^ ((boff >> 3) & 0x70);
        int n = un >> 7, k0 = (un & 127) >> 1;
        uint32_t hp[4], lp[4];
#pragma unroll
        for (int j2 = 0; j2 < 4; j2++) {
            float v0 = (n < 18) ? oW[((size_t)(it * 18 + n) * 256 + (size_t)(chunk * 64 + k0 + j2 * 2)) * 9 + tap] : 0.f;
            float v1 = (n < 18) ? oW[((size_t)(it * 18 + n) * 256 + (size_t)(chunk * 64 + k0 + j2 * 2 + 1)) * 9 + tap] : 0.f;
            split2(v0, v1, hp[j2], lp[j2]);
        }
        char* base = (char*)(g_wOs + (size_t)(((it * 9 + tap) * 4 + chunk) * 2) * 2048);
        *(uint4*)(base + boff)        = make_uint4(hp[0], hp[1], hp[2], hp[3]);
        *(uint4*)(base + 4096 + boff) = make_uint4(lp[0], lp[1], lp[2], lp[3]);
    }
#endif
}

#if HAS_TC
__device__ __forceinline__ void make_record(int m, int k, float dy, float dx)
{
    int b = m >> 12, hw = m & 4095, h = hw >> 6, w = hw & 63;
    float py = dy + (float)(k / 3 - 1) + (float)h;
    float px = dx + (float)(k % 3 - 1) + (float)w;
    float y0f = floorf(py), x0f = floorf(px);
    float wy1 = py - y0f, wy0 = 1.f - wy1;
    float wx1 = px - x0f, wx0 = 1.f - wx1;
    int y0 = (int)y0f, x0 = (int)x0f, y1 = y0 + 1, x1 = x0 + 1;
    int4 ii; float4 ww;
    {
        bool v = (y0 >= 0 && y0 < H_ && x0 >= 0 && x0 < W_);
        int yc = min(max(y0,0),H_-1), xc = min(max(x0,0),W_-1);
        ii.x = ((b << 12) + (yc << 6) + xc) << 8;  ww.x = v ? wy0 * wx0 : 0.f;
    }
    {
        bool v = (y0 >= 0 && y0 < H_ && x1 >= 0 && x1 < W_);
        int yc = min(max(y0,0),H_-1), xc = min(max(x1,0),W_-1);
        ii.y = ((b << 12) + (yc << 6) + xc) << 8;  ww.y = v ? wy0 * wx1 : 0.f;
    }
    {
        bool v = (y1 >= 0 && y1 < H_ && x0 >= 0 && x0 < W_);
        int yc = min(max(y1,0),H_-1), xc = min(max(x0,0),W_-1);
        ii.z = ((b << 12) + (yc << 6) + xc) << 8;  ww.z = v ? wy1 * wx0 : 0.f;
    }
    {
        bool v = (y1 >= 0 && y1 < H_ && x1 >= 0 && x1 < W_);
        int yc = min(max(y1,0),H_-1), xc = min(max(x1,0),W_-1);
        ii.w = ((b << 12) + (yc << 6) + xc) << 8;  ww.w = v ? wy1 * wx1 : 0.f;
    }
    g_recIdx[(size_t)m * 9 + k] = ii;
    g_recW[(size_t)m * 9 + k]   = ww;
}
#endif

// ==== offset conv (N=32): A ring 4, B ring 8 w/ prefetch dist 4 ============
__global__ __launch_bounds__(512, 1)
void offconv_kernel(int fsel, int wsel, float* __restrict__ finalOut)
{
#if HAS_TC
    constexpr int NB = 32 * 128;   // 4 KB per split
    constexpr uint32_t IDESC =
        (1u << 4) | (1u << 7) | (1u << 10) | (4u << 17) | (8u << 24);

    extern __shared__ char smem[];
    const uint32_t sb = smem_u32(smem);
    const int TMEMP = 0, MB_MMA = 16, MB_B = 48, SIDX = 128;
    const int ABASE = 16384;                  // 4 stages x 2 splits x 16KB = 128KB
    const int BBASE = 16384 + 131072;         // 8 stages x 2 splits x 4KB  = 64KB

    const float* __restrict__ fin = fsel ? g_feat1 : g_feat0;
    const __nv_bfloat16* __restrict__ wsrc = g_wOs + (size_t)wsel * 9 * 4 * 2 * 2048;

    const int tid = threadIdx.x, wid = tid >> 5, lid = tid & 31;
    const int bm0 = blockIdx.x * 128;

    if (wid == 0) {
        asm volatile("tcgen05.alloc.cta_group::1.sync.aligned.shared::cta.b32 [%0], %1;"
                     :: "r"(sb + TMEMP), "r"(128u) : "memory");
        asm volatile("tcgen05.relinquish_alloc_permit.cta_group::1.sync.aligned;");
    }
    if (tid < 4) mbar_init(sb + MB_MMA + 8 * tid, 1);
    if (tid < 8) mbar_init(sb + MB_B + 8 * tid, 1);
    for (int t = tid; t < 9 * 128; t += 512) {
        int tap = t >> 7, p = t & 127;
        int m = bm0 + p;
        int b = m >> 12, hw = m & 4095, h = hw >> 6, w = hw & 63;
        int yy = h + tap / 3 - 1, xx = w + tap % 3 - 1;
        ((int*)(smem + SIDX))[t] =
            (yy >= 0 && yy < H_ && xx >= 0 && xx < W_)
                ? (((b << 12) + (yy << 6) + xx) << 8) : -1;
    }
    __syncthreads();
    uint32_t tb;
    asm volatile("ld.shared.b32 %0, [%1];" : "=r"(tb) : "r"(sb + TMEMP));

    // prologue: prefetch B for steps 0..3
    if (tid == 0) {
#pragma unroll
        for (int k = 0; k < 4; k++) {
            mbar_expect_tx(sb + MB_B + 8 * k, 2 * NB);
            bulk_g2s(sb + BBASE + (k * 2 + 0) * NB,
                     (const char*)wsrc + (size_t)(k * 2) * 4096, NB, sb + MB_B + 8 * k);
            bulk_g2s(sb + BBASE + (k * 2 + 1) * NB,
                     (const char*)wsrc + (size_t)(k * 2) * 4096 + NB, NB, sb + MB_B + 8 * k);
        }
    }

    const int grp = tid >> 4;
    const int cl4 = (tid & 15) * 4;
    const int bso = (tid & 15) * 8;

    for (int ks = 0; ks < 36; ++ks) {
        const int tap = ks >> 2, ch = ks & 3;
        const int abuf = ks & 3;
        const int bbuf = ks & 7;
        const int u = ks >> 2;
        if (u > 0) mbar_wait(sb + MB_MMA + 8 * abuf, (u - 1) & 1);

        // prefetch B for step ks+4 (slot (ks+4)&7 was read by MMA(ks-4), done)
        if (tid == 0 && ks + 4 < 36) {
            int kf = ks + 4, bs = kf & 7;
            mbar_expect_tx(sb + MB_B + 8 * bs, 2 * NB);
            bulk_g2s(sb + BBASE + (bs * 2 + 0) * NB,
                     (const char*)wsrc + (size_t)(kf * 2) * 4096, NB, sb + MB_B + 8 * bs);
            bulk_g2s(sb + BBASE + (bs * 2 + 1) * NB,
                     (const char*)wsrc + (size_t)(kf * 2) * 4096 + NB, NB, sb + MB_B + 8 * bs);
        }
        {
            char* ah = smem + ABASE + (abuf * 2 + 0) * 16384;
            char* al = smem + ABASE + (abuf * 2 + 1) * 16384;
            const int co = ch * 64 + cl4;
            const int* sidx = (const int*)(smem + SIDX) + tap * 128;
            int pp0 = grp, pp1 = grp + 64, pp2 = grp + 32, pp3 = grp + 96;
            int b0 = sidx[pp0], b1 = sidx[pp1], b2 = sidx[pp2], b3 = sidx[pp3];
            float4 z = make_float4(0.f,0.f,0.f,0.f);
            float4 r0 = z, r1 = z, r2 = z, r3 = z;
            if (b0 >= 0) r0 = __ldg((const float4*)(fin + b0 + co));
            if (b1 >= 0) r1 = __ldg((const float4*)(fin + b1 + co));
            if (b2 >= 0) r2 = __ldg((const float4*)(fin + b2 + co));
            if (b3 >= 0) r3 = __ldg((const float4*)(fin + b3 + co));
            uint2 hp, lp;
            uint32_t o, s;
            split2(r0.x, r0.y, hp.x, lp.x); split2(r0.z, r0.w, hp.y, lp.y);
            o = (uint32_t)(pp0 * 128 + bso); s = o ^ ((o >> 3) & 0x70);
            *(uint2*)(ah + s) = hp; *(uint2*)(al + s) = lp;
            split2(r1.x, r1.y, hp.x, lp.x); split2(r1.z, r1.w, hp.y, lp.y);
            o = (uint32_t)(pp1 * 128 + bso); s = o ^ ((o >> 3) & 0x70);
            *(uint2*)(ah + s) = hp; *(uint2*)(al + s) = lp;
            split2(r2.x, r2.y, hp.x, lp.x); split2(r2.z, r2.w, hp.y, lp.y);
            o = (uint32_t)(pp2 * 128 + bso); s = o ^ ((o >> 3) & 0x70);
            *(uint2*)(ah + s) = hp; *(uint2*)(al + s) = lp;
            split2(r3.x, r3.y, hp.x, lp.x); split2(r3.z, r3.w, hp.y, lp.y);
            o = (uint32_t)(pp3 * 128 + bso); s = o ^ ((o >> 3) & 0x70);
            *(uint2*)(ah + s) = hp; *(uint2*)(al + s) = lp;
        }
        asm volatile("fence.proxy.async.shared::cta;" ::: "memory");
        __syncthreads();

        if (tid == 0) {
            mbar_wait(sb + MB_B + 8 * bbuf, (ks >> 3) & 1);
            asm volatile("tcgen05.fence::after_thread_sync;" ::: "memory");
            const uint64_t DB = (2ull << 61) | (1ull << 46) | (64ull << 32) | (1ull << 16);
            uint64_t adh = DB | (((sb + ABASE + (abuf * 2 + 0) * 16384) >> 4) & 0x3FFF);
            uint64_t adl = DB | (((sb + ABASE + (abuf * 2 + 1) * 16384) >> 4) & 0x3FFF);
            uint64_t bdh = DB | (((sb + BBASE + (bbuf * 2 + 0) * NB) >> 4) & 0x3FFF);
            uint64_t bdl = DB | (((sb + BBASE + (bbuf * 2 + 1) * NB) >> 4) & 0x3FFF);
#pragma unroll
            for (int k4 = 0; k4 < 4; k4++)
                mma_f16_ss(tb, adh + 2 * k4, bdh + 2 * k4, IDESC, (ks | k4) != 0);
#pragma unroll
            for (int k4 = 0; k4 < 4; k4++)
                mma_f16_ss(tb, adh + 2 * k4, bdl + 2 * k4, IDESC, 1);
#pragma unroll
            for (int k4 = 0; k4 < 4; k4++)
                mma_f16_ss(tb, adl + 2 * k4, bdh + 2 * k4, IDESC, 1);
            tc_commit(sb + MB_MMA + 8 * abuf);
        }
    }

    mbar_wait(sb + MB_MMA + 8 * 3, 0);   // abuf3 9th completion -> parity 0
    asm volatile("tcgen05.fence::after_thread_sync;" ::: "memory");

    if (tid < 128) {
        int m = bm0 + wid * 32 + lid;
        uint32_t r[32];
        LDTM_X32(r, tb);
        asm volatile("tcgen05.wait::ld.sync.aligned;" ::: "memory");
        if (finalOut) {
            int b = m >> 12, hw = m & 4095;
#pragma unroll
            for (int j = 0; j < 18; j++)
                finalOut[((size_t)(b * 18 + j)) * HW_ + hw] = __uint_as_float(r[j]);
        } else {
#pragma unroll
            for (int k = 0; k < 9; k++)
                make_record(m, k, __uint_as_float(r[2 * k]), __uint_as_float(r[2 * k + 1]));
        }
    }
    __syncthreads();
    if (wid == 0)
        asm volatile("tcgen05.dealloc.cta_group::1.sync.aligned.b32 %0, %1;"
                     :: "r"(tb), "r"(128u));
#endif
}

// ==== deform conv (N=256): 2-deep ring, hoisted 16-load gather =============
__global__ __launch_bounds__(512, 1)
void defconv_kernel(int fsel, int wsel)
{
#if HAS_TC
    constexpr int NB = 256 * 128;   // 32 KB per split
    constexpr uint32_t IDESC =
        (1u << 4) | (1u << 7) | (1u << 10) | (32u << 17) | (8u << 24);

    extern __shared__ char smem[];
    const uint32_t sb = smem_u32(smem);
    const int TMEMP = 0, MB_MMA = 16, MB_B = 32;
    const int SIDX = 64;
    const int SWT  = 64 + 4096;
    const int ABASE = 16384;
    const int BBASE = 16384 + 65536;

    const float* __restrict__ fin = fsel ? g_feat1 : g_feat0;
    float* __restrict__ fout      = fsel ? g_feat0 : g_feat1;
    const __nv_bfloat16* __restrict__ wsrc = g_wDs + (size_t)wsel * 9 * 4 * 2 * 16384;

    const int tid = threadIdx.x, wid = tid >> 5, lid = tid & 31;
    const int bm0 = blockIdx.x * 128;

    if (wid == 0) {
        asm volatile("tcgen05.alloc.cta_group::1.sync.aligned.shared::cta.b32 [%0], %1;"
                     :: "r"(sb + TMEMP), "r"(512u) : "memory");
        asm volatile("tcgen05.relinquish_alloc_permit.cta_group::1.sync.aligned;");
    }
    if (tid < 2) { mbar_init(sb + MB_MMA + 8 * tid, 1); mbar_init(sb + MB_B + 8 * tid, 1); }
    if (tid < 128) {
        int m = bm0 + tid;
        ((int4*)(smem + SIDX))[tid]  = g_recIdx[(size_t)m * 9];
        ((float4*)(smem + SWT))[tid] = g_recW[(size_t)m * 9];
    }
    __syncthreads();
    uint32_t tb;
    asm volatile("ld.shared.b32 %0, [%1];" : "=r"(tb) : "r"(sb + TMEMP));

    const int grp = tid >> 4;
    const int cl4 = (tid & 15) * 4;
    const int bso = (tid & 15) * 8;

    for (int ks = 0; ks < 36; ++ks) {
        const int tap = ks >> 2, ch = ks & 3;
        const int buf = ks & 1;
        const int u = ks >> 1;
        if (u > 0) mbar_wait(sb + MB_MMA + 8 * buf, (u - 1) & 1);

        if (tid == 0) {
            mbar_expect_tx(sb + MB_B + 8 * buf, 2 * NB);
            bulk_g2s(sb + BBASE + (buf * 2 + 0) * NB,
                     (const char*)wsrc + (size_t)(ks * 2) * 32768, NB, sb + MB_B + 8 * buf);
            bulk_g2s(sb + BBASE + (buf * 2 + 1) * NB,
                     (const char*)wsrc + (size_t)(ks * 2) * 32768 + NB, NB, sb + MB_B + 8 * buf);
        }
        if (ch == 0 && tap + 1 < 9 && tid < 128) {
            int m = bm0 + tid;
            int r = (tap + 1) & 1;
            ((int4*)(smem + SIDX + r * 2048))[tid]  = g_recIdx[(size_t)m * 9 + tap + 1];
            ((float4*)(smem + SWT + r * 2048))[tid] = g_recW[(size_t)m * 9 + tap + 1];
        }
        {
            char* ah = smem + ABASE + (buf * 2 + 0) * 16384;
            char* al = smem + ABASE + (buf * 2 + 1) * 16384;
            const int co = ch * 64 + cl4;
            const int4*   sI = (const int4*)(smem + SIDX + (tap & 1) * 2048);
            const float4* sW = (const float4*)(smem + SWT + (tap & 1) * 2048);
            int p0 = grp, p1 = grp + 64, p2 = grp + 32, p3 = grp + 96;
            int4   i0 = sI[p0], i1 = sI[p1];
            // ---- hoist all 16 corner loads of the first pixel pair ----
            float4 a0 = __ldg((const float4*)(fin + i0.x + co));
            float4 b0 = __ldg((const float4*)(fin + i0.y + co));
            float4 c0 = __ldg((const float4*)(fin + i0.z + co));
            float4 d0 = __ldg((const float4*)(fin + i0.w + co));
            float4 a1 = __ldg((const float4*)(fin + i1.x + co));
            float4 b1 = __ldg((const float4*)(fin + i1.y + co));
            float4 c1 = __ldg((const float4*)(fin + i1.z + co));
            float4 d1 = __ldg((const float4*)(fin + i1.w + co));
            int4   i2 = sI[p2], i3 = sI[p3];
            float4 a2 = __ldg((const float4*)(fin + i2.x + co));
            float4 b2 = __ldg((const float4*)(fin + i2.y + co));
            float4 c2 = __ldg((const float4*)(fin + i2.z + co));
            float4 d2 = __ldg((const float4*)(fin + i2.w + co));
            float4 a3 = __ldg((const float4*)(fin + i3.x + co));
            float4 b3 = __ldg((const float4*)(fin + i3.y + co));
            float4 c3 = __ldg((const float4*)(fin + i3.z + co));
            float4 d3 = __ldg((const float4*)(fin + i3.w + co));
            float4 w0 = sW[p0], w1 = sW[p1], w2 = sW[p2], w3 = sW[p3];
            float4 r0, r1, r2, r3;
            r0.x = w0.x*a0.x + w0.y*b0.x + w0.z*c0.x + w0.w*d0.x;
            r0.y = w0.x*a0.y + w0.y*b0.y + w0.z*c0.y + w0.w*d0.y;
            r0.z = w0.x*a0.z + w0.y*b0.z + w0.z*c0.z + w0.w*d0.z;
            r0.w = w0.x*a0.w + w0.y*b0.w + w0.z*c0.w + w0.w*d0.w;
            r1.x = w1.x*a1.x + w1.y*b1.x + w1.z*c1.x + w1.w*d1.x;
            r1.y = w1.x*a1.y + w1.y*b1.y + w1.z*c1.y + w1.w*d1.y;
            r1.z = w1.x*a1.z + w1.y*b1.z + w1.z*c1.z + w1.w*d1.z;
            r1.w = w1.x*a1.w + w1.y*b1.w + w1.z*c1.w + w1.w*d1.w;
            r2.x = w2.x*a2.x + w2.y*b2.x + w2.z*c2.x + w2.w*d2.x;
            r2.y = w2.x*a2.y + w2.y*b2.y + w2.z*c2.y + w2.w*d2.y;
            r2.z = w2.x*a2.z + w2.y*b2.z + w2.z*c2.z + w2.w*d2.z;
            r2.w = w2.x*a2.w + w2.y*b2.w + w2.z*c2.w + w2.w*d2.w;
            r3.x = w3.x*a3.x + w3.y*b3.x + w3.z*c3.x + w3.w*d3.x;
            r3.y = w3.x*a3.y + w3.y*b3.y + w3.z*c3.y + w3.w*d3.y;
            r3.z = w3.x*a3.z + w3.y*b3.z + w3.z*c3.z + w3.w*d3.z;
            r3.w = w3.x*a3.w + w3.y*b3.w + w3.z*c3.w + w3.w*d3.w;
            uint2 hp, lp;
            uint32_t o, s;
            split2(r0.x, r0.y, hp.x, lp.x); split2(r0.z, r0.w, hp.y, lp.y);
            o = (uint32_t)(p0 * 128 + bso); s = o ^ ((o >> 3) & 0x70);
            *(uint2*)(ah + s) = hp; *(uint2*)(al + s) = lp;
            split2(r1.x, r1.y, hp.x, lp.x); split2(r1.z, r1.w, hp.y, lp.y);
            o = (uint32_t)(p1 * 128 + bso); s = o ^ ((o >> 3) & 0x70);
            *(uint2*)(ah + s) = hp; *(uint2*)(al + s) = lp;
            split2(r2.x, r2.y, hp.x, lp.x); split2(r2.z, r2.w, hp.y, lp.y);
            o = (uint32_t)(p2 * 128 + bso); s = o ^ ((o >> 3) & 0x70);
            *(uint2*)(ah + s) = hp; *(uint2*)(al + s) = lp;
            split2(r3.x, r3.y, hp.x, lp.x); split2(r3.z, r3.w, hp.y, lp.y);
            o = (uint32_t)(p3 * 128 + bso); s = o ^ ((o >> 3) & 0x70);
            *(uint2*)(ah + s) = hp; *(uint2*)(al + s) = lp;
        }
        asm volatile("fence.proxy.async.shared::cta;" ::: "memory");
        __syncthreads();

        if (tid == 0) {
            mbar_wait(sb + MB_B + 8 * buf, u & 1);
            asm volatile("tcgen05.fence::after_thread_sync;" ::: "memory");
            const uint64_t DB = (2ull << 61) | (1ull << 46) | (64ull << 32) | (1ull << 16);
            uint64_t adh = DB | (((sb + ABASE + (buf * 2 + 0) * 16384) >> 4) & 0x3FFF);
            uint64_t adl = DB | (((sb + ABASE + (buf * 2 + 1) * 16384) >> 4) & 0x3FFF);
            uint64_t bdh = DB | (((sb + BBASE + (buf * 2 + 0) * NB) >> 4) & 0x3FFF);
            uint64_t bdl = DB | (((sb + BBASE + (buf * 2 + 1) * NB) >> 4) & 0x3FFF);
#pragma unroll
            for (int k4 = 0; k4 < 4; k4++)
                mma_f16_ss(tb, adh + 2 * k4, bdh + 2 * k4, IDESC, (ks | k4) != 0);
#pragma unroll
            for (int k4 = 0; k4 < 4; k4++)
                mma_f16_ss(tb, adh + 2 * k4, bdl + 2 * k4, IDESC, 1);
#pragma unroll
            for (int k4 = 0; k4 < 4; k4++)
                mma_f16_ss(tb, adl + 2 * k4, bdh + 2 * k4, IDESC, 1);
            tc_commit(sb + MB_MMA + 8 * buf);
        }
    }

    mbar_wait(sb + MB_MMA + 8, 1);   // buf1 18th completion -> parity 1
    asm volatile("tcgen05.fence::after_thread_sync;" ::: "memory");

    if (tid < 128) {
        int m = bm0 + wid * 32 + lid;
#pragma unroll
        for (int nb = 0; nb < 8; nb++) {
            uint32_t r[32];
            LDTM_X32(r, tb + nb * 32);
            asm volatile("tcgen05.wait::ld.sync.aligned;" ::: "memory");
            float4* dst = (float4*)(fout + (size_t)m * 256 + nb * 32);
#pragma unroll
            for (int q = 0; q < 8; q++)
                dst[q] = make_float4(__uint_as_float(r[q*4+0]), __uint_as_float(r[q*4+1]),
                                     __uint_as_float(r[q*4+2]), __uint_as_float(r[q*4+3]));
        }
    }
    __syncthreads();
    if (wid == 0)
        asm volatile("tcgen05.dealloc.cta_group::1.sync.aligned.b32 %0, %1;"
                     :: "r"(tb), "r"(512u));
#endif
}

// ---------------------------------------------------------------------------
extern "C" void kernel_launch(void* const* d_in, const int* in_sizes, int n_in,
                              void* d_out, int out_size)
{
    (void)in_sizes; (void)n_in; (void)out_size;
    const float* x  = (const float*)d_in[0];
    const float* y  = (const float*)d_in[1];
    const float* oW = (const float*)d_in[2];
    const float* dW = (const float*)d_in[3];
    float* out = (float*)d_out;

    const int SMEM_D = 16384 + 65536 + 131072;          // 212992
    const int SMEM_O = 16384 + 131072 + 8 * 2 * 4096;   // 212992
    cudaFuncSetAttribute(defconv_kernel, cudaFuncAttributeMaxDynamicSharedMemorySize, SMEM_D);
    cudaFuncSetAttribute(offconv_kernel, cudaFuncAttributeMaxDynamicSharedMemorySize, SMEM_O);

    dim3 pb(32, 8), pg(HW_ / 32, C_ / 32, B_);
    pack_kernel<<<pg, pb>>>(x, y);

    const int G = 3 * 9 * 4 * 2048 + 4 * 9 * 4 * 256;
    wsplit_kernel<<<(G + 255) / 256, 256>>>(oW, dW);

    int fsel = 0;
    for (int it = 0; it < 3; ++it) {
        offconv_kernel<<<128, 512, SMEM_O>>>(fsel, it, nullptr);
        defconv_kernel<<<128, 512, SMEM_D>>>(fsel, it);
        fsel ^= 1;
    }
    offconv_kernel<<<128, 512, SMEM_O>>>(fsel, 3, out);
}